// round 1
// baseline (speedup 1.0000x reference)
#include <cuda_runtime.h>

// ======================= device scratch (no cudaMalloc allowed) =======================
__device__ float g_buf0[16*128*128*64];   // enc1 out / dt1 out (64 MB)
__device__ float g_buf1[16*64*64*128];    // enc2 out / decoder work (32 MB)
__device__ float g_buf2[16*64*64*128];    // enc3 out / res work / y_mid
__device__ float g_tmpb[16*64*64*32];     // residual mid
__device__ float g_fbuf[16*64*64*128];    // fallback f
__device__ float g_qbuf[16*64*64*128];    // fallback q
__device__ float g_embT[128*512];         // transposed codebook
__device__ float g_ehalf[512];            // 0.5*||e||^2

// ======================= generic tiled implicit-GEMM conv =======================
// CONV mode : out[m, co] = sum_k im2col(in)[m,k] * w[k, co]   (w is HWIO, K-major rows)
// TCONV mode: stride-2 k=4 transpose conv, decomposed per output parity (blockIdx.z).
template<int BM,int BN,int BK,int TM,int TN,
         int CIN,int COUT,int KH,int KW,int STRIDE,int PAD,
         int INH,int INW,int NB,
         bool RELU_IN,bool HAS_BIAS,bool ADD,bool RELU_OUT,bool TRANS>
__global__ void __launch_bounds__(256)
conv_gemm(const float* __restrict__ in, const float* __restrict__ wgt,
          const float* __restrict__ bias, const float* __restrict__ addsrc,
          float* __restrict__ out)
{
    constexpr int MH = TRANS ? INH : INH / STRIDE;   // M-grid height
    constexpr int MW = TRANS ? INW : INW / STRIDE;   // M-grid width
    constexpr int K  = TRANS ? 4*CIN : KH*KW*CIN;
    constexpr int THREADS = (BM/TM)*(BN/TN);
    static_assert(THREADS == 256, "block must be 256 threads");

    __shared__ __align__(16) float As[BK][BM+4];
    __shared__ __align__(16) float Bs[BK][BN];

    const int tid = threadIdx.x;
    const int m0  = blockIdx.x * BM;
    const int n0  = blockIdx.y * BN;
    const int py  = TRANS ? (int)(blockIdx.z >> 1) : 0;
    const int px  = TRANS ? (int)(blockIdx.z & 1)  : 0;

    const int tcol = tid % (BN/TN);
    const int trow = tid / (BN/TN);

    float acc[TM][TN];
    #pragma unroll
    for (int i = 0; i < TM; i++)
        #pragma unroll
        for (int j = 0; j < TN; j++) acc[i][j] = 0.f;

    for (int k0 = 0; k0 < K; k0 += BK) {
        // ---- A tile (on-the-fly im2col gather, k-inner for coalescing over CIN) ----
        #pragma unroll
        for (int i = 0; i < (BM*BK)/THREADS; i++) {
            int l = tid + i*THREADS;
            int mloc = l / BK, kloc = l % BK;
            int m = m0 + mloc;
            int k = k0 + kloc;
            int mx = m % MW; int t = m / MW; int my = t % MH; int n = t / MH;
            float v = 0.f;
            if (TRANS) {
                int ci = k % CIN; int ab = k / CIN;
                int bb = ab & 1, aa = ab >> 1;
                int iy = my + py + aa - 1;
                int ix = mx + px + bb - 1;
                if (iy >= 0 && iy < INH && ix >= 0 && ix < INW)
                    v = in[((n*INH + iy)*INW + ix)*CIN + ci];
            } else {
                int ci = k % CIN; int r = k / CIN;
                int kw = r % KW, kh = r / KW;
                int iy = my*STRIDE - PAD + kh;
                int ix = mx*STRIDE - PAD + kw;
                if (iy >= 0 && iy < INH && ix >= 0 && ix < INW)
                    v = in[((n*INH + iy)*INW + ix)*CIN + ci];
            }
            if (RELU_IN) v = fmaxf(v, 0.f);
            As[kloc][mloc] = v;
        }
        // ---- B tile (weights; HWIO rows are already [k, co] contiguous) ----
        #pragma unroll
        for (int i = 0; i < (BK*BN)/THREADS; i++) {
            int l = tid + i*THREADS;
            int kloc = l / BN, nloc = l % BN;
            int k = k0 + kloc;
            float v;
            if (TRANS) {
                int ci = k % CIN; int ab = k / CIN;
                int bb = ab & 1, aa = ab >> 1;
                int widx = ((2*aa + py)*KW + (2*bb + px))*CIN + ci;
                v = wgt[widx*COUT + n0 + nloc];
            } else {
                v = wgt[k*COUT + n0 + nloc];
            }
            Bs[kloc][nloc] = v;
        }
        __syncthreads();
        #pragma unroll
        for (int kk = 0; kk < BK; kk++) {
            float ra[TM], rb[TN];
            #pragma unroll
            for (int i = 0; i < TM; i += 4) {
                float4 t4 = *reinterpret_cast<const float4*>(&As[kk][trow*TM + i]);
                ra[i]=t4.x; ra[i+1]=t4.y; ra[i+2]=t4.z; ra[i+3]=t4.w;
            }
            #pragma unroll
            for (int j = 0; j < TN; j += 4) {
                float4 t4 = *reinterpret_cast<const float4*>(&Bs[kk][tcol*TN + j]);
                rb[j]=t4.x; rb[j+1]=t4.y; rb[j+2]=t4.z; rb[j+3]=t4.w;
            }
            #pragma unroll
            for (int i = 0; i < TM; i++)
                #pragma unroll
                for (int j = 0; j < TN; j++)
                    acc[i][j] += ra[i]*rb[j];
        }
        __syncthreads();
    }
    // ---- epilogue ----
    #pragma unroll
    for (int i = 0; i < TM; i++) {
        int m = m0 + trow*TM + i;
        int obase;
        if (TRANS) {
            int mx = m % MW; int t = m / MW; int my = t % MH; int n = t / MH;
            obase = ((n*(2*INH) + 2*my + py)*(2*INW) + 2*mx + px)*COUT;
        } else {
            obase = m*COUT;
        }
        #pragma unroll
        for (int j = 0; j < TN; j++) {
            int c = n0 + tcol*TN + j;
            float v = acc[i][j];
            if (HAS_BIAS) v += bias[c];
            if (ADD)      v += addsrc[obase + c];
            if (RELU_OUT) v = fmaxf(v, 0.f);
            out[obase + c] = v;
        }
    }
}

// ======================= codebook prep: transpose + half-norms =======================
__global__ void emb_prep(const float* __restrict__ emb,
                         float* __restrict__ embT, float* __restrict__ ehalf)
{
    int c = blockIdx.x;          // 512 codes
    int k = threadIdx.x;         // 128 dims
    float v = emb[c*128 + k];
    embT[k*512 + c] = v;
    float s = v*v;
    #pragma unroll
    for (int o = 16; o; o >>= 1) s += __shfl_xor_sync(0xffffffffu, s, o);
    __shared__ float red[4];
    if ((k & 31) == 0) red[k >> 5] = s;
    __syncthreads();
    if (k == 0) ehalf[c] = 0.5f*(red[0]+red[1]+red[2]+red[3]);
}

// ======================= VQ: argmin over 512 codes + gather =======================
// Per block: 32 rows x all 512 codes, K=128. score = f.e - 0.5||e||^2, argmax, first-index ties.
__global__ void __launch_bounds__(256)
vq_kernel(const float* __restrict__ f, const float* __restrict__ emb,
          const float* __restrict__ embT, const float* __restrict__ ehalf,
          float* __restrict__ q)
{
    __shared__ __align__(16) float As[16][36];
    __shared__ __align__(16) float Bs[16][512];
    __shared__ float bv[32][17];
    __shared__ int   bi[32][17];
    __shared__ int   rowIdx[32];

    const int tid = threadIdx.x;
    const int tx  = tid & 15;   // 16 code-groups (stride-16 interleave)
    const int ty  = tid >> 4;   // 16 row-pairs
    const int m0  = blockIdx.x * 32;

    float acc0[32], acc1[32];
    #pragma unroll
    for (int j = 0; j < 32; j++) { acc0[j] = 0.f; acc1[j] = 0.f; }

    for (int k0 = 0; k0 < 128; k0 += 16) {
        #pragma unroll
        for (int i = 0; i < 2; i++) {
            int l = tid + i*256;
            As[l & 15][l >> 4] = f[(m0 + (l >> 4))*128 + k0 + (l & 15)];
        }
        #pragma unroll
        for (int i = 0; i < 32; i++) {
            int l = tid + i*256;
            Bs[l >> 9][l & 511] = embT[(k0 + (l >> 9))*512 + (l & 511)];
        }
        __syncthreads();
        #pragma unroll
        for (int kk = 0; kk < 16; kk++) {
            float ra0 = As[kk][ty*2], ra1 = As[kk][ty*2 + 1];
            #pragma unroll
            for (int j = 0; j < 32; j++) {
                float rb = Bs[kk][tx + (j << 4)];
                acc0[j] += ra0*rb; acc1[j] += ra1*rb;
            }
        }
        __syncthreads();
    }
    {
        float b0 = -3.4e38f, b1 = -3.4e38f; int i0 = 0, i1 = 0;
        #pragma unroll
        for (int j = 0; j < 32; j++) {
            int code = tx + (j << 4);
            float h = __ldg(&ehalf[code]);
            float s0 = acc0[j] - h;
            float s1 = acc1[j] - h;
            if (s0 > b0 || (s0 == b0 && code < i0)) { b0 = s0; i0 = code; }
            if (s1 > b1 || (s1 == b1 && code < i1)) { b1 = s1; i1 = code; }
        }
        bv[ty*2][tx] = b0;  bi[ty*2][tx] = i0;
        bv[ty*2+1][tx] = b1; bi[ty*2+1][tx] = i1;
    }
    __syncthreads();
    if (tid < 32) {
        float best = -3.4e38f; int bidx = 0;
        #pragma unroll
        for (int t2 = 0; t2 < 16; t2++) {
            float s = bv[tid][t2]; int c = bi[tid][t2];
            if (s > best || (s == best && c < bidx)) { best = s; bidx = c; }
        }
        rowIdx[tid] = bidx;
    }
    __syncthreads();
    for (int l = tid; l < 32*128; l += 256) {
        int r = l >> 7, j = l & 127;
        q[(m0 + r)*128 + j] = emb[rowIdx[r]*128 + j];
    }
}

// ======================= dt2: 4x4 s2 transpose conv, 64 -> 3, direct =======================
// Per-parity grid.z: weight taps uniform per block -> smem weight reads broadcast.
__global__ void __launch_bounds__(256)
dt2_kernel(const float* __restrict__ in,  // [16,128,128,64]
           const float* __restrict__ wgt, // [4,4,64,3]
           const float* __restrict__ bias,
           float* __restrict__ out)       // [16,256,256,3]
{
    __shared__ float ws[4*4*64*3];
    for (int l = threadIdx.x; l < 3072; l += 256) ws[l] = wgt[l];
    __syncthreads();

    const int py = blockIdx.z >> 1, px = blockIdx.z & 1;
    const int m = blockIdx.x * 256 + threadIdx.x;     // over 16*128*128
    const int xq = m & 127; int t = m >> 7; const int yq = t & 127; const int n = t >> 7;

    float a0 = __ldg(&bias[0]), a1 = __ldg(&bias[1]), a2 = __ldg(&bias[2]);
    #pragma unroll
    for (int aa = 0; aa < 2; aa++) {
        #pragma unroll
        for (int bb = 0; bb < 2; bb++) {
            int iy = yq + py + aa - 1;
            int ix = xq + px + bb - 1;
            if (iy < 0 || iy >= 128 || ix < 0 || ix >= 128) continue;
            const float* ip = in + ((n*128 + iy)*128 + ix)*64;
            const float* wp = ws + ((2*aa + py)*4 + (2*bb + px))*64*3;
            #pragma unroll
            for (int ci = 0; ci < 64; ci += 4) {
                float4 v = *reinterpret_cast<const float4*>(ip + ci);
                const float* w0 = wp + ci*3;
                a0 += v.x*w0[0];  a1 += v.x*w0[1];  a2 += v.x*w0[2];
                a0 += v.y*w0[3];  a1 += v.y*w0[4];  a2 += v.y*w0[5];
                a0 += v.z*w0[6];  a1 += v.z*w0[7];  a2 += v.z*w0[8];
                a0 += v.w*w0[9];  a1 += v.w*w0[10]; a2 += v.w*w0[11];
            }
        }
    }
    const int oy = 2*yq + py, ox = 2*xq + px;
    float* op = out + ((n*256 + oy)*256 + ox)*3;
    op[0] = a0; op[1] = a1; op[2] = a2;
}

// ======================= host launcher =======================
extern "C" void kernel_launch(void* const* d_in, const int* in_sizes, int n_in,
                              void* d_out, int out_size)
{
    (void)in_sizes; (void)n_in;
    const float* x       = (const float*)d_in[0];
    const float* emb     = (const float*)d_in[1];
    const float* enc_w1  = (const float*)d_in[2];
    const float* enc_b1  = (const float*)d_in[3];
    const float* enc_w2  = (const float*)d_in[4];
    const float* enc_b2  = (const float*)d_in[5];
    const float* enc_w3  = (const float*)d_in[6];
    const float* enc_b3  = (const float*)d_in[7];
    const float* erb1_w1 = (const float*)d_in[8];
    const float* erb1_w2 = (const float*)d_in[9];
    const float* erb2_w1 = (const float*)d_in[10];
    const float* erb2_w2 = (const float*)d_in[11];
    const float* dec_w   = (const float*)d_in[12];
    const float* dec_b   = (const float*)d_in[13];
    const float* drb1_w1 = (const float*)d_in[14];
    const float* drb1_w2 = (const float*)d_in[15];
    const float* drb2_w1 = (const float*)d_in[16];
    const float* drb2_w2 = (const float*)d_in[17];
    const float* dt1_w   = (const float*)d_in[18];
    const float* dt1_b   = (const float*)d_in[19];
    const float* dt2_w   = (const float*)d_in[20];
    const float* dt2_b   = (const float*)d_in[21];

    float* out = (float*)d_out;
    const int YS = 16*256*256*3;
    const int FS = 16*64*64*128;

    float *buf0,*buf1,*buf2,*tmpb,*embT,*ehalf,*fb,*qb;
    cudaGetSymbolAddress((void**)&buf0,  g_buf0);
    cudaGetSymbolAddress((void**)&buf1,  g_buf1);
    cudaGetSymbolAddress((void**)&buf2,  g_buf2);
    cudaGetSymbolAddress((void**)&tmpb,  g_tmpb);
    cudaGetSymbolAddress((void**)&embT,  g_embT);
    cudaGetSymbolAddress((void**)&ehalf, g_ehalf);
    cudaGetSymbolAddress((void**)&fb,    g_fbuf);
    cudaGetSymbolAddress((void**)&qb,    g_qbuf);

    const bool full = (out_size >= YS + 2*FS);
    float* fptr = full ? (out + YS)      : fb;
    float* qptr = full ? (out + YS + FS) : qb;

    dim3 b(256);

    // ---- encoder ----
    // enc1: 4x4 s2, 3->64, 256->128, bias+relu
    conv_gemm<64,64,16,4,4,  3,64,4,4,2,1, 256,256,16, false,true,false,true,false>
        <<<dim3(4096,1,1),b>>>(x, enc_w1, enc_b1, nullptr, buf0);
    // enc2: 4x4 s2, 64->128, 128->64, bias+relu
    conv_gemm<128,128,16,8,8, 64,128,4,4,2,1, 128,128,16, false,true,false,true,false>
        <<<dim3(512,1,1),b>>>(buf0, enc_w2, enc_b2, nullptr, buf1);
    // enc3: 3x3 s1, 128->128, bias
    conv_gemm<128,128,16,8,8, 128,128,3,3,1,1, 64,64,16, false,true,false,false,false>
        <<<dim3(512,1,1),b>>>(buf1, enc_w3, enc_b3, nullptr, buf2);
    // residual block 1
    conv_gemm<128,32,16,4,4, 128,32,3,3,1,1, 64,64,16, true,false,false,true,false>
        <<<dim3(512,1,1),b>>>(buf2, erb1_w1, nullptr, nullptr, tmpb);
    conv_gemm<128,128,16,8,8, 32,128,1,1,1,0, 64,64,16, false,false,true,false,false>
        <<<dim3(512,1,1),b>>>(tmpb, erb1_w2, nullptr, buf2, buf2);
    // residual block 2 (+ final stack relu) -> f
    conv_gemm<128,32,16,4,4, 128,32,3,3,1,1, 64,64,16, true,false,false,true,false>
        <<<dim3(512,1,1),b>>>(buf2, erb2_w1, nullptr, nullptr, tmpb);
    conv_gemm<128,128,16,8,8, 32,128,1,1,1,0, 64,64,16, false,false,true,true,false>
        <<<dim3(512,1,1),b>>>(tmpb, erb2_w2, nullptr, buf2, fptr);

    // ---- VQ ----
    emb_prep<<<512,128>>>(emb, embT, ehalf);
    vq_kernel<<<2048,256>>>(fptr, emb, embT, ehalf, qptr);

    // ---- decoder ----
    conv_gemm<128,128,16,8,8, 128,128,3,3,1,1, 64,64,16, false,true,false,false,false>
        <<<dim3(512,1,1),b>>>(qptr, dec_w, dec_b, nullptr, buf1);
    conv_gemm<128,32,16,4,4, 128,32,3,3,1,1, 64,64,16, true,false,false,true,false>
        <<<dim3(512,1,1),b>>>(buf1, drb1_w1, nullptr, nullptr, tmpb);
    conv_gemm<128,128,16,8,8, 32,128,1,1,1,0, 64,64,16, false,false,true,false,false>
        <<<dim3(512,1,1),b>>>(tmpb, drb1_w2, nullptr, buf1, buf1);
    conv_gemm<128,32,16,4,4, 128,32,3,3,1,1, 64,64,16, true,false,false,true,false>
        <<<dim3(512,1,1),b>>>(buf1, drb2_w1, nullptr, nullptr, tmpb);
    conv_gemm<128,128,16,8,8, 32,128,1,1,1,0, 64,64,16, false,false,true,true,false>
        <<<dim3(512,1,1),b>>>(tmpb, drb2_w2, nullptr, buf1, buf2);

    // ---- upsample ----
    // dt1: tconv 4x4 s2, 128->64, 64->128, bias+relu (parity via grid.z)
    conv_gemm<128,64,16,8,4, 128,64,4,4,2,0, 64,64,16, false,true,false,true,true>
        <<<dim3(512,1,4),b>>>(buf2, dt1_w, dt1_b, nullptr, buf0);
    // dt2: tconv 4x4 s2, 64->3, 128->256, bias -> y
    dt2_kernel<<<dim3(1024,1,4),b>>>(buf0, dt2_w, dt2_b, out);
}

// round 3
// speedup vs baseline: 1.4085x; 1.4085x over previous
#include <cuda_runtime.h>
#include <cstdint>

// ======================= device scratch (no cudaMalloc allowed) =======================
__device__ float g_buf0[16*128*128*64];   // enc1 out / dt1 out (64 MB)
__device__ float g_buf1[16*64*64*128];    // enc2 out / decoder work (32 MB)
__device__ float g_buf2[16*64*64*128];    // enc3 out / res work / y_mid
__device__ float g_tmpb[16*64*64*32];     // residual mid
__device__ float g_fbuf[16*64*64*128];    // fallback f
__device__ float g_qbuf[16*64*64*128];    // fallback q
__device__ float g_embT[128*512];         // transposed codebook
__device__ float g_ehalf[512];            // 0.5*||e||^2

__device__ __forceinline__ uint32_t f2tf32(float x) {
    uint32_t r; asm("cvt.rna.tf32.f32 %0, %1;" : "=r"(r) : "f"(x)); return r;
}
__device__ __forceinline__ void mma_tf32(float* d, const uint32_t* a, const uint32_t* b) {
    asm volatile(
        "mma.sync.aligned.m16n8k8.row.col.f32.tf32.tf32.f32 "
        "{%0,%1,%2,%3}, {%4,%5,%6,%7}, {%8,%9}, {%0,%1,%2,%3};"
        : "+f"(d[0]), "+f"(d[1]), "+f"(d[2]), "+f"(d[3])
        : "r"(a[0]), "r"(a[1]), "r"(a[2]), "r"(a[3]), "r"(b[0]), "r"(b[1]));
}

// ======================= fp32 tiled implicit-GEMM conv (encoder path) =======================
template<int BM,int BN,int BK,int TM,int TN,
         int CIN,int COUT,int KH,int KW,int STRIDE,int PAD,
         int INH,int INW,int NB,
         bool RELU_IN,bool HAS_BIAS,bool ADD,bool RELU_OUT,bool TRANS>
__global__ void __launch_bounds__(256)
conv_gemm(const float* __restrict__ in, const float* __restrict__ wgt,
          const float* __restrict__ bias, const float* __restrict__ addsrc,
          float* __restrict__ out)
{
    constexpr int MH = TRANS ? INH : INH / STRIDE;
    constexpr int MW = TRANS ? INW : INW / STRIDE;
    constexpr int K  = TRANS ? 4*CIN : KH*KW*CIN;
    constexpr int THREADS = (BM/TM)*(BN/TN);
    static_assert(THREADS == 256, "block must be 256 threads");

    __shared__ __align__(16) float As[BK][BM+4];
    __shared__ __align__(16) float Bs[BK][BN];

    const int tid = threadIdx.x;
    const int m0  = blockIdx.x * BM;
    const int n0  = blockIdx.y * BN;
    const int py  = TRANS ? (int)(blockIdx.z >> 1) : 0;
    const int px  = TRANS ? (int)(blockIdx.z & 1)  : 0;

    const int tcol = tid % (BN/TN);
    const int trow = tid / (BN/TN);

    float acc[TM][TN];
    #pragma unroll
    for (int i = 0; i < TM; i++)
        #pragma unroll
        for (int j = 0; j < TN; j++) acc[i][j] = 0.f;

    for (int k0 = 0; k0 < K; k0 += BK) {
        #pragma unroll
        for (int i = 0; i < (BM*BK)/THREADS; i++) {
            int l = tid + i*THREADS;
            int mloc = l / BK, kloc = l % BK;
            int m = m0 + mloc;
            int k = k0 + kloc;
            int mx = m % MW; int t = m / MW; int my = t % MH; int n = t / MH;
            float v = 0.f;
            if (TRANS) {
                int ci = k % CIN; int ab = k / CIN;
                int bb = ab & 1, aa = ab >> 1;
                int iy = my + py + aa - 1;
                int ix = mx + px + bb - 1;
                if (iy >= 0 && iy < INH && ix >= 0 && ix < INW)
                    v = in[((n*INH + iy)*INW + ix)*CIN + ci];
            } else {
                int ci = k % CIN; int r = k / CIN;
                int kw = r % KW, kh = r / KW;
                int iy = my*STRIDE - PAD + kh;
                int ix = mx*STRIDE - PAD + kw;
                if (iy >= 0 && iy < INH && ix >= 0 && ix < INW)
                    v = in[((n*INH + iy)*INW + ix)*CIN + ci];
            }
            if (RELU_IN) v = fmaxf(v, 0.f);
            As[kloc][mloc] = v;
        }
        #pragma unroll
        for (int i = 0; i < (BK*BN)/THREADS; i++) {
            int l = tid + i*THREADS;
            int kloc = l / BN, nloc = l % BN;
            int k = k0 + kloc;
            float v;
            if (TRANS) {
                int ci = k % CIN; int ab = k / CIN;
                int bb = ab & 1, aa = ab >> 1;
                int widx = ((2*aa + py)*KW + (2*bb + px))*CIN + ci;
                v = wgt[widx*COUT + n0 + nloc];
            } else {
                v = wgt[k*COUT + n0 + nloc];
            }
            Bs[kloc][nloc] = v;
        }
        __syncthreads();
        #pragma unroll
        for (int kk = 0; kk < BK; kk++) {
            float ra[TM], rb[TN];
            #pragma unroll
            for (int i = 0; i < TM; i += 4) {
                float4 t4 = *reinterpret_cast<const float4*>(&As[kk][trow*TM + i]);
                ra[i]=t4.x; ra[i+1]=t4.y; ra[i+2]=t4.z; ra[i+3]=t4.w;
            }
            #pragma unroll
            for (int j = 0; j < TN; j += 4) {
                float4 t4 = *reinterpret_cast<const float4*>(&Bs[kk][tcol*TN + j]);
                rb[j]=t4.x; rb[j+1]=t4.y; rb[j+2]=t4.z; rb[j+3]=t4.w;
            }
            #pragma unroll
            for (int i = 0; i < TM; i++)
                #pragma unroll
                for (int j = 0; j < TN; j++)
                    acc[i][j] += ra[i]*rb[j];
        }
        __syncthreads();
    }
    #pragma unroll
    for (int i = 0; i < TM; i++) {
        int m = m0 + trow*TM + i;
        int obase;
        if (TRANS) {
            int mx = m % MW; int t = m / MW; int my = t % MH; int n = t / MH;
            obase = ((n*(2*INH) + 2*my + py)*(2*INW) + 2*mx + px)*COUT;
        } else {
            obase = m*COUT;
        }
        #pragma unroll
        for (int j = 0; j < TN; j++) {
            int c = n0 + tcol*TN + j;
            float v = acc[i][j];
            if (HAS_BIAS) v += bias[c];
            if (ADD)      v += addsrc[obase + c];
            if (RELU_OUT) v = fmaxf(v, 0.f);
            out[obase + c] = v;
        }
    }
}

// ======================= tf32 mma.sync implicit-GEMM conv (decoder path) =======================
// D[128/block, COUT] = im2col(in) @ w, fp32 accumulate, tf32 inputs (RN-rounded).
// m16n8k8 fragment layout:
//   A: a0=(r=t/4,   k=t%4)  a1=(r+8, k)  a2=(r, k+4)  a3=(r+8, k+4)
//   B: b0=(k=t%4, n=t/4)    b1=(k+4, n)
//   D: d0=(r, 2(t%4)) d1=(r, +1) d2=(r+8, 2(t%4)) d3=(r+8, +1)
// Smem banks: As stride 36 -> bank 4*(t/4)+(t%4) distinct; Bs stride BN+8 -> 8*(t%4)+(t/4) distinct.
template<int CIN,int COUT,int KH,int KW,int STRIDE,int PAD,int INH,int INW,
         bool RELU_IN,bool HAS_BIAS,bool ADD,bool RELU_OUT,bool TRANS>
__global__ void __launch_bounds__(256)
mma_conv(const float* __restrict__ in, const float* __restrict__ wgt,
         const float* __restrict__ bias, const float* __restrict__ addsrc,
         float* __restrict__ out)
{
    constexpr int MH = TRANS ? INH : INH / STRIDE;
    constexpr int MW = TRANS ? INW : INW / STRIDE;
    constexpr int K  = TRANS ? 4*CIN : KH*KW*CIN;
    constexpr int BM = 128, BK = 32, BN = COUT;
    constexpr int WARPS_N = (BN >= 64) ? 2 : 1;
    constexpr int WARPS_M = 8 / WARPS_N;
    constexpr int WM = BM / WARPS_M;        // 32 or 16
    constexpr int WN = BN / WARPS_N;        // 64 or 32
    constexpr int MF = WM / 16;
    constexpr int NF = WN / 8;
    constexpr int ASTR = BK + 4;            // 36
    constexpr int BSTR = BN + 8;

    __shared__ __align__(16) uint32_t As[BM][ASTR];
    __shared__ __align__(16) uint32_t Bs[BK][BSTR];

    const int tid  = threadIdx.x;
    const int wid  = tid >> 5;
    const int lane = tid & 31;
    const int m0   = blockIdx.x * BM;
    const int py   = TRANS ? (int)(blockIdx.z >> 1) : 0;
    const int px   = TRANS ? (int)(blockIdx.z & 1)  : 0;
    const int wm   = wid / WARPS_N;
    const int wn   = wid % WARPS_N;
    const int lr   = lane >> 2;   // 0..7
    const int lc   = lane & 3;    // 0..3

    float acc[MF][NF][4];
    #pragma unroll
    for (int i = 0; i < MF; i++)
        #pragma unroll
        for (int j = 0; j < NF; j++)
            #pragma unroll
            for (int r = 0; r < 4; r++) acc[i][j][r] = 0.f;

    for (int k0 = 0; k0 < K; k0 += BK) {
        // ---- A tile: 128 rows x 32 k (float4 gathers, im2col on the fly) ----
        #pragma unroll
        for (int it = 0; it < 4; it++) {
            int l = tid + it*256;
            int m = l >> 3, kq = l & 7;
            int k = k0 + kq*4;
            int mg = m0 + m;
            int mx = mg % MW; int t = mg / MW; int my = t % MH; int n = t / MH;
            float4 v = make_float4(0.f,0.f,0.f,0.f);
            int iy, ix, ci;
            if (TRANS) {
                ci = k % CIN; int ab = k / CIN;
                int bb = ab & 1, aa = ab >> 1;
                iy = my + py + aa - 1;
                ix = mx + px + bb - 1;
            } else {
                ci = k % CIN; int r = k / CIN;
                int kw = r % KW, kh = r / KW;
                iy = my*STRIDE - PAD + kh;
                ix = mx*STRIDE - PAD + kw;
            }
            if (iy >= 0 && iy < INH && ix >= 0 && ix < INW)
                v = *reinterpret_cast<const float4*>(&in[((n*INH + iy)*INW + ix)*CIN + ci]);
            if (RELU_IN) {
                v.x = fmaxf(v.x, 0.f); v.y = fmaxf(v.y, 0.f);
                v.z = fmaxf(v.z, 0.f); v.w = fmaxf(v.w, 0.f);
            }
            uint4 tv;
            tv.x = f2tf32(v.x); tv.y = f2tf32(v.y); tv.z = f2tf32(v.z); tv.w = f2tf32(v.w);
            *reinterpret_cast<uint4*>(&As[m][kq*4]) = tv;
        }
        // ---- B tile: 32 k x COUT (float4 over cout) ----
        #pragma unroll
        for (int it = 0; it < (BK*BN)/(4*256); it++) {
            int l = tid + it*256;
            int co = (l % (BN/4))*4;
            int kk = l / (BN/4);
            int k = k0 + kk;
            float4 w;
            if (TRANS) {
                int ci = k % CIN; int ab = k / CIN;
                int bb = ab & 1, aa = ab >> 1;
                int widx = ((2*aa + py)*KW + (2*bb + px))*CIN + ci;
                w = *reinterpret_cast<const float4*>(&wgt[widx*COUT + co]);
            } else {
                w = *reinterpret_cast<const float4*>(&wgt[k*COUT + co]);
            }
            uint4 tw;
            tw.x = f2tf32(w.x); tw.y = f2tf32(w.y); tw.z = f2tf32(w.z); tw.w = f2tf32(w.w);
            *reinterpret_cast<uint4*>(&Bs[kk][co]) = tw;
        }
        __syncthreads();
        // ---- compute: 4 k-steps of 8 ----
        #pragma unroll
        for (int ks = 0; ks < BK; ks += 8) {
            uint32_t a[MF][4];
            #pragma unroll
            for (int i = 0; i < MF; i++) {
                int r = wm*WM + i*16 + lr;
                a[i][0] = As[r    ][ks + lc];
                a[i][1] = As[r + 8][ks + lc];
                a[i][2] = As[r    ][ks + lc + 4];
                a[i][3] = As[r + 8][ks + lc + 4];
            }
            uint32_t bfr[NF][2];
            #pragma unroll
            for (int j = 0; j < NF; j++) {
                int c = wn*WN + j*8 + lr;
                bfr[j][0] = Bs[ks + lc    ][c];
                bfr[j][1] = Bs[ks + lc + 4][c];
            }
            #pragma unroll
            for (int i = 0; i < MF; i++)
                #pragma unroll
                for (int j = 0; j < NF; j++)
                    mma_tf32(acc[i][j], a[i], bfr[j]);
        }
        __syncthreads();
    }
    // ---- epilogue: fuse bias/add/relu, float2 stores ----
    #pragma unroll
    for (int i = 0; i < MF; i++) {
        int r0 = m0 + wm*WM + i*16 + lr;
        #pragma unroll
        for (int half = 0; half < 2; half++) {
            int mg = r0 + half*8;
            int obase;
            if (TRANS) {
                int mx = mg % MW; int t = mg / MW; int my = t % MH; int n = t / MH;
                obase = ((n*(2*INH) + 2*my + py)*(2*INW) + 2*mx + px)*COUT;
            } else {
                obase = mg*COUT;
            }
            #pragma unroll
            for (int j = 0; j < NF; j++) {
                int c = wn*WN + j*8 + 2*lc;
                float v0 = acc[i][j][half*2 + 0];
                float v1 = acc[i][j][half*2 + 1];
                if (HAS_BIAS) {
                    float2 bv = *reinterpret_cast<const float2*>(&bias[c]);
                    v0 += bv.x; v1 += bv.y;
                }
                if (ADD) {
                    float2 av = *reinterpret_cast<const float2*>(&addsrc[obase + c]);
                    v0 += av.x; v1 += av.y;
                }
                if (RELU_OUT) { v0 = fmaxf(v0, 0.f); v1 = fmaxf(v1, 0.f); }
                float2 ov; ov.x = v0; ov.y = v1;
                *reinterpret_cast<float2*>(&out[obase + c]) = ov;
            }
        }
    }
}

// ======================= codebook prep =======================
__global__ void emb_prep(const float* __restrict__ emb,
                         float* __restrict__ embT, float* __restrict__ ehalf)
{
    int c = blockIdx.x;
    int k = threadIdx.x;
    float v = emb[c*128 + k];
    embT[k*512 + c] = v;
    float s = v*v;
    #pragma unroll
    for (int o = 16; o; o >>= 1) s += __shfl_xor_sync(0xffffffffu, s, o);
    __shared__ float red[4];
    if ((k & 31) == 0) red[k >> 5] = s;
    __syncthreads();
    if (k == 0) ehalf[c] = 0.5f*(red[0]+red[1]+red[2]+red[3]);
}

// ======================= VQ =======================
__global__ void __launch_bounds__(256)
vq_kernel(const float* __restrict__ f, const float* __restrict__ emb,
          const float* __restrict__ embT, const float* __restrict__ ehalf,
          float* __restrict__ q)
{
    __shared__ __align__(16) float As[16][36];
    __shared__ __align__(16) float Bs[16][512];
    __shared__ float bv[32][17];
    __shared__ int   bi[32][17];
    __shared__ int   rowIdx[32];

    const int tid = threadIdx.x;
    const int tx  = tid & 15;
    const int ty  = tid >> 4;
    const int m0  = blockIdx.x * 32;

    float acc0[32], acc1[32];
    #pragma unroll
    for (int j = 0; j < 32; j++) { acc0[j] = 0.f; acc1[j] = 0.f; }

    for (int k0 = 0; k0 < 128; k0 += 16) {
        #pragma unroll
        for (int i = 0; i < 2; i++) {
            int l = tid + i*256;
            As[l & 15][l >> 4] = f[(m0 + (l >> 4))*128 + k0 + (l & 15)];
        }
        #pragma unroll
        for (int i = 0; i < 32; i++) {
            int l = tid + i*256;
            Bs[l >> 9][l & 511] = embT[(k0 + (l >> 9))*512 + (l & 511)];
        }
        __syncthreads();
        #pragma unroll
        for (int kk = 0; kk < 16; kk++) {
            float ra0 = As[kk][ty*2], ra1 = As[kk][ty*2 + 1];
            #pragma unroll
            for (int j = 0; j < 32; j++) {
                float rb = Bs[kk][tx + (j << 4)];
                acc0[j] += ra0*rb; acc1[j] += ra1*rb;
            }
        }
        __syncthreads();
    }
    {
        float b0 = -3.4e38f, b1 = -3.4e38f; int i0 = 0, i1 = 0;
        #pragma unroll
        for (int j = 0; j < 32; j++) {
            int code = tx + (j << 4);
            float h = __ldg(&ehalf[code]);
            float s0 = acc0[j] - h;
            float s1 = acc1[j] - h;
            if (s0 > b0 || (s0 == b0 && code < i0)) { b0 = s0; i0 = code; }
            if (s1 > b1 || (s1 == b1 && code < i1)) { b1 = s1; i1 = code; }
        }
        bv[ty*2][tx] = b0;  bi[ty*2][tx] = i0;
        bv[ty*2+1][tx] = b1; bi[ty*2+1][tx] = i1;
    }
    __syncthreads();
    if (tid < 32) {
        float best = -3.4e38f; int bidx = 0;
        #pragma unroll
        for (int t2 = 0; t2 < 16; t2++) {
            float s = bv[tid][t2]; int c = bi[tid][t2];
            if (s > best || (s == best && c < bidx)) { best = s; bidx = c; }
        }
        rowIdx[tid] = bidx;
    }
    __syncthreads();
    for (int l = tid; l < 32*128; l += 256) {
        int r = l >> 7, j = l & 127;
        q[(m0 + r)*128 + j] = emb[rowIdx[r]*128 + j];
    }
}

// ======================= dt2: 4x4 s2 tconv 64->3, direct =======================
__global__ void __launch_bounds__(256)
dt2_kernel(const float* __restrict__ in,
           const float* __restrict__ wgt,
           const float* __restrict__ bias,
           float* __restrict__ out)
{
    __shared__ float ws[4*4*64*3];
    for (int l = threadIdx.x; l < 3072; l += 256) ws[l] = wgt[l];
    __syncthreads();

    const int py = blockIdx.z >> 1, px = blockIdx.z & 1;
    const int m = blockIdx.x * 256 + threadIdx.x;
    const int xq = m & 127; int t = m >> 7; const int yq = t & 127; const int n = t >> 7;

    float a0 = __ldg(&bias[0]), a1 = __ldg(&bias[1]), a2 = __ldg(&bias[2]);
    #pragma unroll
    for (int aa = 0; aa < 2; aa++) {
        #pragma unroll
        for (int bb = 0; bb < 2; bb++) {
            int iy = yq + py + aa - 1;
            int ix = xq + px + bb - 1;
            if (iy < 0 || iy >= 128 || ix < 0 || ix >= 128) continue;
            const float* ip = in + ((n*128 + iy)*128 + ix)*64;
            const float* wp = ws + ((2*aa + py)*4 + (2*bb + px))*64*3;
            #pragma unroll
            for (int ci = 0; ci < 64; ci += 4) {
                float4 v = *reinterpret_cast<const float4*>(ip + ci);
                const float* w0 = wp + ci*3;
                a0 += v.x*w0[0];  a1 += v.x*w0[1];  a2 += v.x*w0[2];
                a0 += v.y*w0[3];  a1 += v.y*w0[4];  a2 += v.y*w0[5];
                a0 += v.z*w0[6];  a1 += v.z*w0[7];  a2 += v.z*w0[8];
                a0 += v.w*w0[9];  a1 += v.w*w0[10]; a2 += v.w*w0[11];
            }
        }
    }
    const int oy = 2*yq + py, ox = 2*xq + px;
    float* op = out + ((n*256 + oy)*256 + ox)*3;
    op[0] = a0; op[1] = a1; op[2] = a2;
}

// ======================= host launcher =======================
extern "C" void kernel_launch(void* const* d_in, const int* in_sizes, int n_in,
                              void* d_out, int out_size)
{
    (void)in_sizes; (void)n_in;
    const float* x       = (const float*)d_in[0];
    const float* emb     = (const float*)d_in[1];
    const float* enc_w1  = (const float*)d_in[2];
    const float* enc_b1  = (const float*)d_in[3];
    const float* enc_w2  = (const float*)d_in[4];
    const float* enc_b2  = (const float*)d_in[5];
    const float* enc_w3  = (const float*)d_in[6];
    const float* enc_b3  = (const float*)d_in[7];
    const float* erb1_w1 = (const float*)d_in[8];
    const float* erb1_w2 = (const float*)d_in[9];
    const float* erb2_w1 = (const float*)d_in[10];
    const float* erb2_w2 = (const float*)d_in[11];
    const float* dec_w   = (const float*)d_in[12];
    const float* dec_b   = (const float*)d_in[13];
    const float* drb1_w1 = (const float*)d_in[14];
    const float* drb1_w2 = (const float*)d_in[15];
    const float* drb2_w1 = (const float*)d_in[16];
    const float* drb2_w2 = (const float*)d_in[17];
    const float* dt1_w   = (const float*)d_in[18];
    const float* dt1_b   = (const float*)d_in[19];
    const float* dt2_w   = (const float*)d_in[20];
    const float* dt2_b   = (const float*)d_in[21];

    float* out = (float*)d_out;
    const int YS = 16*256*256*3;
    const int FS = 16*64*64*128;

    float *buf0,*buf1,*buf2,*tmpb,*embT,*ehalf,*fb,*qb;
    cudaGetSymbolAddress((void**)&buf0,  g_buf0);
    cudaGetSymbolAddress((void**)&buf1,  g_buf1);
    cudaGetSymbolAddress((void**)&buf2,  g_buf2);
    cudaGetSymbolAddress((void**)&tmpb,  g_tmpb);
    cudaGetSymbolAddress((void**)&embT,  g_embT);
    cudaGetSymbolAddress((void**)&ehalf, g_ehalf);
    cudaGetSymbolAddress((void**)&fb,    g_fbuf);
    cudaGetSymbolAddress((void**)&qb,    g_qbuf);

    const bool full = (out_size >= YS + 2*FS);
    float* fptr = full ? (out + YS)      : fb;
    float* qptr = full ? (out + YS + FS) : qb;

    dim3 b(256);

    // ---- encoder (fp32 — VQ argmin needs ~1e-5 accuracy in f) ----
    conv_gemm<64,64,16,4,4,  3,64,4,4,2,1, 256,256,16, false,true,false,true,false>
        <<<dim3(4096,1,1),b>>>(x, enc_w1, enc_b1, nullptr, buf0);
    conv_gemm<128,128,16,8,8, 64,128,4,4,2,1, 128,128,16, false,true,false,true,false>
        <<<dim3(512,1,1),b>>>(buf0, enc_w2, enc_b2, nullptr, buf1);
    conv_gemm<128,128,16,8,8, 128,128,3,3,1,1, 64,64,16, false,true,false,false,false>
        <<<dim3(512,1,1),b>>>(buf1, enc_w3, enc_b3, nullptr, buf2);
    conv_gemm<128,32,16,4,4, 128,32,3,3,1,1, 64,64,16, true,false,false,true,false>
        <<<dim3(512,1,1),b>>>(buf2, erb1_w1, nullptr, nullptr, tmpb);
    conv_gemm<128,128,16,8,8, 32,128,1,1,1,0, 64,64,16, false,false,true,false,false>
        <<<dim3(512,1,1),b>>>(tmpb, erb1_w2, nullptr, buf2, buf2);
    conv_gemm<128,32,16,4,4, 128,32,3,3,1,1, 64,64,16, true,false,false,true,false>
        <<<dim3(512,1,1),b>>>(buf2, erb2_w1, nullptr, nullptr, tmpb);
    conv_gemm<128,128,16,8,8, 32,128,1,1,1,0, 64,64,16, false,false,true,true,false>
        <<<dim3(512,1,1),b>>>(tmpb, erb2_w2, nullptr, buf2, fptr);

    // ---- VQ (fp32, exact) ----
    emb_prep<<<512,128>>>(emb, embT, ehalf);
    vq_kernel<<<2048,256>>>(fptr, emb, embT, ehalf, qptr);

    // ---- decoder (tf32 mma.sync, fp32 accum; y tolerance 1e-3 >> tf32 error ~5e-4) ----
    mma_conv<128,128,3,3,1,1, 64,64, false,true,false,false,false>
        <<<dim3(512,1,1),b>>>(qptr, dec_w, dec_b, nullptr, buf1);
    mma_conv<128,32, 3,3,1,1, 64,64, true,false,false,true,false>
        <<<dim3(512,1,1),b>>>(buf1, drb1_w1, nullptr, nullptr, tmpb);
    mma_conv<32,128, 1,1,1,0, 64,64, false,false,true,false,false>
        <<<dim3(512,1,1),b>>>(tmpb, drb1_w2, nullptr, buf1, buf1);
    mma_conv<128,32, 3,3,1,1, 64,64, true,false,false,true,false>
        <<<dim3(512,1,1),b>>>(buf1, drb2_w1, nullptr, nullptr, tmpb);
    mma_conv<32,128, 1,1,1,0, 64,64, false,false,true,true,false>
        <<<dim3(512,1,1),b>>>(tmpb, drb2_w2, nullptr, buf1, buf2);
    mma_conv<128,64, 4,4,2,0, 64,64, false,true,false,true,true>
        <<<dim3(512,1,4),b>>>(buf2, dt1_w, dt1_b, nullptr, buf0);

    dt2_kernel<<<dim3(1024,1,4),b>>>(buf0, dt2_w, dt2_b, out);
}

// round 4
// speedup vs baseline: 1.9187x; 1.3622x over previous
#include <cuda_runtime.h>
#include <cstdint>

// ======================= device scratch (no cudaMalloc allowed) =======================
__device__ float g_buf0[16*128*128*64];   // enc1 out / dt1 out (64 MB)
__device__ float g_buf1[16*64*64*128];    // enc2 out / decoder work (32 MB)
__device__ float g_buf2[16*64*64*128];    // enc3 out / res work / y_mid
__device__ float g_tmpb[16*64*64*32];     // residual mid
__device__ float g_fbuf[16*64*64*128];    // fallback f
__device__ float g_qbuf[16*64*64*128];    // fallback q
__device__ float g_embT[128*512];         // transposed codebook
__device__ float g_ehalf[512];            // 0.5*||e||^2

__device__ __forceinline__ uint32_t f2tf32(float x) {
    uint32_t r; asm("cvt.rna.tf32.f32 %0, %1;" : "=r"(r) : "f"(x)); return r;
}
__device__ __forceinline__ void mma_tf32(float* d, const uint32_t* a, const uint32_t* b) {
    asm volatile(
        "mma.sync.aligned.m16n8k8.row.col.f32.tf32.tf32.f32 "
        "{%0,%1,%2,%3}, {%4,%5,%6,%7}, {%8,%9}, {%0,%1,%2,%3};"
        : "+f"(d[0]), "+f"(d[1]), "+f"(d[2]), "+f"(d[3])
        : "r"(a[0]), "r"(a[1]), "r"(a[2]), "r"(a[3]), "r"(b[0]), "r"(b[1]));
}
__device__ __forceinline__ uint32_t smem_u32(const void* p) {
    uint32_t a;
    asm("{ .reg .u64 t; cvta.to.shared.u64 t, %1; cvt.u32.u64 %0, t; }" : "=r"(a) : "l"(p));
    return a;
}
__device__ __forceinline__ void cp_async16(uint32_t saddr, const void* gaddr, int src_sz) {
    asm volatile("cp.async.cg.shared.global [%0], [%1], 16, %2;"
                 :: "r"(saddr), "l"(gaddr), "r"(src_sz) : "memory");
}
#define CP_COMMIT() asm volatile("cp.async.commit_group;" ::: "memory")
#define CP_WAIT1()  asm volatile("cp.async.wait_group 1;" ::: "memory")

// ======================= fp32 tiled implicit-GEMM conv (enc1 only) =======================
template<int BM,int BN,int BK,int TM,int TN,
         int CIN,int COUT,int KH,int KW,int STRIDE,int PAD,
         int INH,int INW,int NB,
         bool RELU_IN,bool HAS_BIAS,bool ADD,bool RELU_OUT,bool TRANS>
__global__ void __launch_bounds__(256)
conv_gemm(const float* __restrict__ in, const float* __restrict__ wgt,
          const float* __restrict__ bias, const float* __restrict__ addsrc,
          float* __restrict__ out)
{
    constexpr int MH = TRANS ? INH : INH / STRIDE;
    constexpr int MW = TRANS ? INW : INW / STRIDE;
    constexpr int K  = TRANS ? 4*CIN : KH*KW*CIN;
    constexpr int THREADS = (BM/TM)*(BN/TN);
    static_assert(THREADS == 256, "block must be 256 threads");

    __shared__ __align__(16) float As[BK][BM+4];
    __shared__ __align__(16) float Bs[BK][BN];

    const int tid = threadIdx.x;
    const int m0  = blockIdx.x * BM;
    const int n0  = blockIdx.y * BN;
    const int py  = TRANS ? (int)(blockIdx.z >> 1) : 0;
    const int px  = TRANS ? (int)(blockIdx.z & 1)  : 0;

    const int tcol = tid % (BN/TN);
    const int trow = tid / (BN/TN);

    float acc[TM][TN];
    #pragma unroll
    for (int i = 0; i < TM; i++)
        #pragma unroll
        for (int j = 0; j < TN; j++) acc[i][j] = 0.f;

    for (int k0 = 0; k0 < K; k0 += BK) {
        #pragma unroll
        for (int i = 0; i < (BM*BK)/THREADS; i++) {
            int l = tid + i*THREADS;
            int mloc = l / BK, kloc = l % BK;
            int m = m0 + mloc;
            int k = k0 + kloc;
            int mx = m % MW; int t = m / MW; int my = t % MH; int n = t / MH;
            float v = 0.f;
            if (TRANS) {
                int ci = k % CIN; int ab = k / CIN;
                int bb = ab & 1, aa = ab >> 1;
                int iy = my + py + aa - 1;
                int ix = mx + px + bb - 1;
                if (iy >= 0 && iy < INH && ix >= 0 && ix < INW)
                    v = in[((n*INH + iy)*INW + ix)*CIN + ci];
            } else {
                int ci = k % CIN; int r = k / CIN;
                int kw = r % KW, kh = r / KW;
                int iy = my*STRIDE - PAD + kh;
                int ix = mx*STRIDE - PAD + kw;
                if (iy >= 0 && iy < INH && ix >= 0 && ix < INW)
                    v = in[((n*INH + iy)*INW + ix)*CIN + ci];
            }
            if (RELU_IN) v = fmaxf(v, 0.f);
            As[kloc][mloc] = v;
        }
        #pragma unroll
        for (int i = 0; i < (BK*BN)/THREADS; i++) {
            int l = tid + i*THREADS;
            int kloc = l / BN, nloc = l % BN;
            int k = k0 + kloc;
            float v;
            if (TRANS) {
                int ci = k % CIN; int ab = k / CIN;
                int bb = ab & 1, aa = ab >> 1;
                int widx = ((2*aa + py)*KW + (2*bb + px))*CIN + ci;
                v = wgt[widx*COUT + n0 + nloc];
            } else {
                v = wgt[k*COUT + n0 + nloc];
            }
            Bs[kloc][nloc] = v;
        }
        __syncthreads();
        #pragma unroll
        for (int kk = 0; kk < BK; kk++) {
            float ra[TM], rb[TN];
            #pragma unroll
            for (int i = 0; i < TM; i += 4) {
                float4 t4 = *reinterpret_cast<const float4*>(&As[kk][trow*TM + i]);
                ra[i]=t4.x; ra[i+1]=t4.y; ra[i+2]=t4.z; ra[i+3]=t4.w;
            }
            #pragma unroll
            for (int j = 0; j < TN; j += 4) {
                float4 t4 = *reinterpret_cast<const float4*>(&Bs[kk][tcol*TN + j]);
                rb[j]=t4.x; rb[j+1]=t4.y; rb[j+2]=t4.z; rb[j+3]=t4.w;
            }
            #pragma unroll
            for (int i = 0; i < TM; i++)
                #pragma unroll
                for (int j = 0; j < TN; j++)
                    acc[i][j] += ra[i]*rb[j];
        }
        __syncthreads();
    }
    #pragma unroll
    for (int i = 0; i < TM; i++) {
        int m = m0 + trow*TM + i;
        int obase;
        if (TRANS) {
            int mx = m % MW; int t = m / MW; int my = t % MH; int n = t / MH;
            obase = ((n*(2*INH) + 2*my + py)*(2*INW) + 2*mx + px)*COUT;
        } else {
            obase = m*COUT;
        }
        #pragma unroll
        for (int j = 0; j < TN; j++) {
            int c = n0 + tcol*TN + j;
            float v = acc[i][j];
            if (HAS_BIAS) v += bias[c];
            if (ADD)      v += addsrc[obase + c];
            if (RELU_OUT) v = fmaxf(v, 0.f);
            out[obase + c] = v;
        }
    }
}

// ============ pipelined tf32 mma.sync implicit-GEMM conv (cp.async, 2-stage) ============
// Raw fp32 tiles in smem (cp.async zfill for OOB), tf32 conversion at fragment load.
// SPLIT=1: single-pass tf32 (decoder). SPLIT=3: 3xTF32 hi/lo split (encoder, ~fp32 precision):
//   D += a_lo*b_hi + a_hi*b_lo + a_hi*b_hi  (per-product error ~2^-22).
template<int CIN,int COUT,int KH,int KW,int STRIDE,int PAD,int INH,int INW,
         bool RELU_IN,bool HAS_BIAS,bool ADD,bool RELU_OUT,bool TRANS,int SPLIT>
__global__ void __launch_bounds__(256)
mma_conv2(const float* __restrict__ in, const float* __restrict__ wgt,
          const float* __restrict__ bias, const float* __restrict__ addsrc,
          float* __restrict__ out)
{
    constexpr int MH = TRANS ? INH : INH / STRIDE;
    constexpr int MW = TRANS ? INW : INW / STRIDE;
    constexpr int K  = TRANS ? 4*CIN : KH*KW*CIN;
    constexpr int BM = 128, BK = 32, BN = COUT;
    constexpr int S  = K / BK;
    constexpr int WARPS_N = (BN >= 64) ? 2 : 1;
    constexpr int WARPS_M = 8 / WARPS_N;
    constexpr int WM = BM / WARPS_M;
    constexpr int WN = BN / WARPS_N;
    constexpr int MF = WM / 16;
    constexpr int NF = WN / 8;
    constexpr int ASTR = BK + 4;       // 36 words/row (16B-aligned rows)
    constexpr int BSTR = BN + 8;
    constexpr int A_WORDS = BM*ASTR;   // per stage
    constexpr int B_WORDS = BK*BSTR;

    extern __shared__ __align__(16) float smem[];
    float* AsF = smem;                   // [2][BM][ASTR]
    float* BsF = smem + 2*A_WORDS;       // [2][BK][BSTR]
    const uint32_t sb    = smem_u32(smem);
    const uint32_t sbB   = sb + 2*A_WORDS*4;

    const int tid  = threadIdx.x;
    const int wid  = tid >> 5;
    const int lane = tid & 31;
    const int m0   = blockIdx.x * BM;
    const int py   = TRANS ? (int)(blockIdx.z >> 1) : 0;
    const int px   = TRANS ? (int)(blockIdx.z & 1)  : 0;
    const int wm   = wid / WARPS_N;
    const int wn   = wid % WARPS_N;
    const int lr   = lane >> 2;
    const int lc   = lane & 3;

    float acc[MF][NF][4];
    #pragma unroll
    for (int i = 0; i < MF; i++)
        #pragma unroll
        for (int j = 0; j < NF; j++)
            #pragma unroll
            for (int r = 0; r < 4; r++) acc[i][j][r] = 0.f;

    // ---- async tile loader for k-slab s into buffer s&1 ----
    auto load_tile = [&](int s) {
        if (s >= S) return;
        const int buf = s & 1;
        const int k0  = s * BK;
        // A: 128 rows x 32 k, 4 x float4 per thread
        #pragma unroll
        for (int it = 0; it < 4; it++) {
            int l = tid + it*256;
            int m = l >> 3, kq = l & 7;
            int k = k0 + kq*4;
            int mg = m0 + m;
            int mx = mg % MW; int t = mg / MW; int my = t % MH; int n = t / MH;
            int iy, ix, ci;
            if (TRANS) {
                ci = k % CIN; int ab = k / CIN;
                int bb = ab & 1, aa = ab >> 1;
                iy = my + py + aa - 1;
                ix = mx + px + bb - 1;
            } else {
                ci = k % CIN; int r = k / CIN;
                int kw = r % KW, kh = r / KW;
                iy = my*STRIDE - PAD + kh;
                ix = mx*STRIDE - PAD + kw;
            }
            bool ok = (iy >= 0 && iy < INH && ix >= 0 && ix < INW);
            const float* gp = ok ? &in[((n*INH + iy)*INW + ix)*CIN + ci] : in;
            uint32_t sa = sb + (uint32_t)((buf*A_WORDS + m*ASTR + kq*4) * 4);
            cp_async16(sa, gp, ok ? 16 : 0);
        }
        // B: 32 k x BN, (BK*BN/4)/256 x float4 per thread
        #pragma unroll
        for (int it = 0; it < (BK*BN)/(4*256); it++) {
            int l = tid + it*256;
            int co = (l % (BN/4))*4;
            int kk = l / (BN/4);
            int k = k0 + kk;
            const float* gp;
            if (TRANS) {
                int ci = k % CIN; int ab = k / CIN;
                int bb = ab & 1, aa = ab >> 1;
                int widx = ((2*aa + py)*KW + (2*bb + px))*CIN + ci;
                gp = &wgt[widx*COUT + co];
            } else {
                gp = &wgt[k*COUT + co];
            }
            uint32_t sa = sbB + (uint32_t)((buf*B_WORDS + kk*BSTR + co) * 4);
            cp_async16(sa, gp, 16);
        }
    };

    load_tile(0); CP_COMMIT();
    load_tile(1); CP_COMMIT();

    for (int s = 0; s < S; s++) {
        CP_WAIT1();
        __syncthreads();
        const int buf = s & 1;
        const float* A = AsF + buf*A_WORDS;
        const float* B = BsF + buf*B_WORDS;
        #pragma unroll
        for (int ks = 0; ks < BK; ks += 8) {
            uint32_t ah[MF][4], al[MF][4];
            #pragma unroll
            for (int i = 0; i < MF; i++) {
                int r = wm*WM + i*16 + lr;
                float v0 = A[(r    )*ASTR + ks + lc];
                float v1 = A[(r + 8)*ASTR + ks + lc];
                float v2 = A[(r    )*ASTR + ks + lc + 4];
                float v3 = A[(r + 8)*ASTR + ks + lc + 4];
                if (RELU_IN) {
                    v0 = fmaxf(v0, 0.f); v1 = fmaxf(v1, 0.f);
                    v2 = fmaxf(v2, 0.f); v3 = fmaxf(v3, 0.f);
                }
                ah[i][0] = f2tf32(v0); ah[i][1] = f2tf32(v1);
                ah[i][2] = f2tf32(v2); ah[i][3] = f2tf32(v3);
                if (SPLIT == 3) {
                    al[i][0] = f2tf32(v0 - __uint_as_float(ah[i][0]));
                    al[i][1] = f2tf32(v1 - __uint_as_float(ah[i][1]));
                    al[i][2] = f2tf32(v2 - __uint_as_float(ah[i][2]));
                    al[i][3] = f2tf32(v3 - __uint_as_float(ah[i][3]));
                }
            }
            #pragma unroll
            for (int j = 0; j < NF; j++) {
                int c = wn*WN + j*8 + lr;
                float w0 = B[(ks + lc    )*BSTR + c];
                float w1 = B[(ks + lc + 4)*BSTR + c];
                uint32_t bh[2], bl[2];
                bh[0] = f2tf32(w0); bh[1] = f2tf32(w1);
                if (SPLIT == 3) {
                    bl[0] = f2tf32(w0 - __uint_as_float(bh[0]));
                    bl[1] = f2tf32(w1 - __uint_as_float(bh[1]));
                }
                #pragma unroll
                for (int i = 0; i < MF; i++) {
                    if (SPLIT == 3) {
                        mma_tf32(acc[i][j], al[i], bh);
                        mma_tf32(acc[i][j], ah[i], bl);
                    }
                    mma_tf32(acc[i][j], ah[i], bh);
                }
            }
        }
        __syncthreads();
        load_tile(s + 2); CP_COMMIT();
    }

    // ---- epilogue: fuse bias/add/relu, float2 stores ----
    #pragma unroll
    for (int i = 0; i < MF; i++) {
        int r0 = m0 + wm*WM + i*16 + lr;
        #pragma unroll
        for (int half = 0; half < 2; half++) {
            int mg = r0 + half*8;
            int obase;
            if (TRANS) {
                int mx = mg % MW; int t = mg / MW; int my = t % MH; int n = t / MH;
                obase = ((n*(2*INH) + 2*my + py)*(2*INW) + 2*mx + px)*COUT;
            } else {
                obase = mg*COUT;
            }
            #pragma unroll
            for (int j = 0; j < NF; j++) {
                int c = wn*WN + j*8 + 2*lc;
                float v0 = acc[i][j][half*2 + 0];
                float v1 = acc[i][j][half*2 + 1];
                if (HAS_BIAS) {
                    float2 bv = *reinterpret_cast<const float2*>(&bias[c]);
                    v0 += bv.x; v1 += bv.y;
                }
                if (ADD) {
                    float2 av = *reinterpret_cast<const float2*>(&addsrc[obase + c]);
                    v0 += av.x; v1 += av.y;
                }
                if (RELU_OUT) { v0 = fmaxf(v0, 0.f); v1 = fmaxf(v1, 0.f); }
                float2 ov; ov.x = v0; ov.y = v1;
                *reinterpret_cast<float2*>(&out[obase + c]) = ov;
            }
        }
    }
}

// ======================= codebook prep =======================
__global__ void emb_prep(const float* __restrict__ emb,
                         float* __restrict__ embT, float* __restrict__ ehalf)
{
    int c = blockIdx.x;
    int k = threadIdx.x;
    float v = emb[c*128 + k];
    embT[k*512 + c] = v;
    float s = v*v;
    #pragma unroll
    for (int o = 16; o; o >>= 1) s += __shfl_xor_sync(0xffffffffu, s, o);
    __shared__ float red[4];
    if ((k & 31) == 0) red[k >> 5] = s;
    __syncthreads();
    if (k == 0) ehalf[c] = 0.5f*(red[0]+red[1]+red[2]+red[3]);
}

// ======================= VQ =======================
__global__ void __launch_bounds__(256)
vq_kernel(const float* __restrict__ f, const float* __restrict__ emb,
          const float* __restrict__ embT, const float* __restrict__ ehalf,
          float* __restrict__ q)
{
    __shared__ __align__(16) float As[16][36];
    __shared__ __align__(16) float Bs[16][512];
    __shared__ float bv[32][17];
    __shared__ int   bi[32][17];
    __shared__ int   rowIdx[32];

    const int tid = threadIdx.x;
    const int tx  = tid & 15;
    const int ty  = tid >> 4;
    const int m0  = blockIdx.x * 32;

    float acc0[32], acc1[32];
    #pragma unroll
    for (int j = 0; j < 32; j++) { acc0[j] = 0.f; acc1[j] = 0.f; }

    for (int k0 = 0; k0 < 128; k0 += 16) {
        #pragma unroll
        for (int i = 0; i < 2; i++) {
            int l = tid + i*256;
            As[l & 15][l >> 4] = f[(m0 + (l >> 4))*128 + k0 + (l & 15)];
        }
        #pragma unroll
        for (int i = 0; i < 32; i++) {
            int l = tid + i*256;
            Bs[l >> 9][l & 511] = embT[(k0 + (l >> 9))*512 + (l & 511)];
        }
        __syncthreads();
        #pragma unroll
        for (int kk = 0; kk < 16; kk++) {
            float ra0 = As[kk][ty*2], ra1 = As[kk][ty*2 + 1];
            #pragma unroll
            for (int j = 0; j < 32; j++) {
                float rb = Bs[kk][tx + (j << 4)];
                acc0[j] += ra0*rb; acc1[j] += ra1*rb;
            }
        }
        __syncthreads();
    }
    {
        float b0 = -3.4e38f, b1 = -3.4e38f; int i0 = 0, i1 = 0;
        #pragma unroll
        for (int j = 0; j < 32; j++) {
            int code = tx + (j << 4);
            float h = __ldg(&ehalf[code]);
            float s0 = acc0[j] - h;
            float s1 = acc1[j] - h;
            if (s0 > b0 || (s0 == b0 && code < i0)) { b0 = s0; i0 = code; }
            if (s1 > b1 || (s1 == b1 && code < i1)) { b1 = s1; i1 = code; }
        }
        bv[ty*2][tx] = b0;  bi[ty*2][tx] = i0;
        bv[ty*2+1][tx] = b1; bi[ty*2+1][tx] = i1;
    }
    __syncthreads();
    if (tid < 32) {
        float best = -3.4e38f; int bidx = 0;
        #pragma unroll
        for (int t2 = 0; t2 < 16; t2++) {
            float s = bv[tid][t2]; int c = bi[tid][t2];
            if (s > best || (s == best && c < bidx)) { best = s; bidx = c; }
        }
        rowIdx[tid] = bidx;
    }
    __syncthreads();
    for (int l = tid; l < 32*128; l += 256) {
        int r = l >> 7, j = l & 127;
        q[(m0 + r)*128 + j] = emb[rowIdx[r]*128 + j];
    }
}

// ======================= dt2: 4x4 s2 tconv 64->3, direct =======================
__global__ void __launch_bounds__(256)
dt2_kernel(const float* __restrict__ in,
           const float* __restrict__ wgt,
           const float* __restrict__ bias,
           float* __restrict__ out)
{
    __shared__ float ws[4*4*64*3];
    for (int l = threadIdx.x; l < 3072; l += 256) ws[l] = wgt[l];
    __syncthreads();

    const int py = blockIdx.z >> 1, px = blockIdx.z & 1;
    const int m = blockIdx.x * 256 + threadIdx.x;
    const int xq = m & 127; int t = m >> 7; const int yq = t & 127; const int n = t >> 7;

    float a0 = __ldg(&bias[0]), a1 = __ldg(&bias[1]), a2 = __ldg(&bias[2]);
    #pragma unroll
    for (int aa = 0; aa < 2; aa++) {
        #pragma unroll
        for (int bb = 0; bb < 2; bb++) {
            int iy = yq + py + aa - 1;
            int ix = xq + px + bb - 1;
            if (iy < 0 || iy >= 128 || ix < 0 || ix >= 128) continue;
            const float* ip = in + ((n*128 + iy)*128 + ix)*64;
            const float* wp = ws + ((2*aa + py)*4 + (2*bb + px))*64*3;
            #pragma unroll
            for (int ci = 0; ci < 64; ci += 4) {
                float4 v = *reinterpret_cast<const float4*>(ip + ci);
                const float* w0 = wp + ci*3;
                a0 += v.x*w0[0];  a1 += v.x*w0[1];  a2 += v.x*w0[2];
                a0 += v.y*w0[3];  a1 += v.y*w0[4];  a2 += v.y*w0[5];
                a0 += v.z*w0[6];  a1 += v.z*w0[7];  a2 += v.z*w0[8];
                a0 += v.w*w0[9];  a1 += v.w*w0[10]; a2 += v.w*w0[11];
            }
        }
    }
    const int oy = 2*yq + py, ox = 2*xq + px;
    float* op = out + ((n*256 + oy)*256 + ox)*3;
    op[0] = a0; op[1] = a1; op[2] = a2;
}

// ======================= host launcher =======================
extern "C" void kernel_launch(void* const* d_in, const int* in_sizes, int n_in,
                              void* d_out, int out_size)
{
    (void)in_sizes; (void)n_in;
    const float* x       = (const float*)d_in[0];
    const float* emb     = (const float*)d_in[1];
    const float* enc_w1  = (const float*)d_in[2];
    const float* enc_b1  = (const float*)d_in[3];
    const float* enc_w2  = (const float*)d_in[4];
    const float* enc_b2  = (const float*)d_in[5];
    const float* enc_w3  = (const float*)d_in[6];
    const float* enc_b3  = (const float*)d_in[7];
    const float* erb1_w1 = (const float*)d_in[8];
    const float* erb1_w2 = (const float*)d_in[9];
    const float* erb2_w1 = (const float*)d_in[10];
    const float* erb2_w2 = (const float*)d_in[11];
    const float* dec_w   = (const float*)d_in[12];
    const float* dec_b   = (const float*)d_in[13];
    const float* drb1_w1 = (const float*)d_in[14];
    const float* drb1_w2 = (const float*)d_in[15];
    const float* drb2_w1 = (const float*)d_in[16];
    const float* drb2_w2 = (const float*)d_in[17];
    const float* dt1_w   = (const float*)d_in[18];
    const float* dt1_b   = (const float*)d_in[19];
    const float* dt2_w   = (const float*)d_in[20];
    const float* dt2_b   = (const float*)d_in[21];

    float* out = (float*)d_out;
    const int YS = 16*256*256*3;
    const int FS = 16*64*64*128;

    float *buf0,*buf1,*buf2,*tmpb,*embT,*ehalf,*fb,*qb;
    cudaGetSymbolAddress((void**)&buf0,  g_buf0);
    cudaGetSymbolAddress((void**)&buf1,  g_buf1);
    cudaGetSymbolAddress((void**)&buf2,  g_buf2);
    cudaGetSymbolAddress((void**)&tmpb,  g_tmpb);
    cudaGetSymbolAddress((void**)&embT,  g_embT);
    cudaGetSymbolAddress((void**)&ehalf, g_ehalf);
    cudaGetSymbolAddress((void**)&fb,    g_fbuf);
    cudaGetSymbolAddress((void**)&qb,    g_qbuf);

    const bool full = (out_size >= YS + 2*FS);
    float* fptr = full ? (out + YS)      : fb;
    float* qptr = full ? (out + YS + FS) : qb;

    dim3 b(256);

    // dynamic smem: 2*(128*36 + 32*(BN+8))*4 bytes
    const int SMN128 = 2*(128*36 + 32*136)*4;  // 71680
    const int SMN64  = 2*(128*36 + 32*72)*4;   // 55296
    const int SMN32  = 2*(128*36 + 32*40)*4;   // 47104

    // ---- encoder (3xTF32: per-product error ~2^-22, same scale as fp32 reassoc) ----
    auto kEnc2 = mma_conv2<64,128,4,4,2,1, 128,128, false,true,false,true,false,3>;
    auto kEnc3 = mma_conv2<128,128,3,3,1,1, 64,64, false,true,false,false,false,3>;
    auto kEw1  = mma_conv2<128,32, 3,3,1,1, 64,64, true,false,false,true,false,3>;
    auto kEw2  = mma_conv2<32,128, 1,1,1,0, 64,64, false,false,true,false,false,3>;
    auto kEw2R = mma_conv2<32,128, 1,1,1,0, 64,64, false,false,true,true,false,3>;
    // ---- decoder (single-pass tf32) ----
    auto kDec  = mma_conv2<128,128,3,3,1,1, 64,64, false,true,false,false,false,1>;
    auto kDw1  = mma_conv2<128,32, 3,3,1,1, 64,64, true,false,false,true,false,1>;
    auto kDw2  = mma_conv2<32,128, 1,1,1,0, 64,64, false,false,true,false,false,1>;
    auto kDw2R = mma_conv2<32,128, 1,1,1,0, 64,64, false,false,true,true,false,1>;
    auto kDt1  = mma_conv2<128,64, 4,4,2,0, 64,64, false,true,false,true,true,1>;

    cudaFuncSetAttribute(kEnc2, cudaFuncAttributeMaxDynamicSharedMemorySize, SMN128);
    cudaFuncSetAttribute(kEnc3, cudaFuncAttributeMaxDynamicSharedMemorySize, SMN128);
    cudaFuncSetAttribute(kEw1,  cudaFuncAttributeMaxDynamicSharedMemorySize, SMN32);
    cudaFuncSetAttribute(kEw2,  cudaFuncAttributeMaxDynamicSharedMemorySize, SMN128);
    cudaFuncSetAttribute(kEw2R, cudaFuncAttributeMaxDynamicSharedMemorySize, SMN128);
    cudaFuncSetAttribute(kDec,  cudaFuncAttributeMaxDynamicSharedMemorySize, SMN128);
    cudaFuncSetAttribute(kDw1,  cudaFuncAttributeMaxDynamicSharedMemorySize, SMN32);
    cudaFuncSetAttribute(kDw2,  cudaFuncAttributeMaxDynamicSharedMemorySize, SMN128);
    cudaFuncSetAttribute(kDw2R, cudaFuncAttributeMaxDynamicSharedMemorySize, SMN128);
    cudaFuncSetAttribute(kDt1,  cudaFuncAttributeMaxDynamicSharedMemorySize, SMN64);

    // ---- encoder ----
    conv_gemm<64,64,16,4,4,  3,64,4,4,2,1, 256,256,16, false,true,false,true,false>
        <<<dim3(4096,1,1),b>>>(x, enc_w1, enc_b1, nullptr, buf0);
    kEnc2<<<dim3(512,1,1), b, SMN128>>>(buf0, enc_w2, enc_b2, nullptr, buf1);
    kEnc3<<<dim3(512,1,1), b, SMN128>>>(buf1, enc_w3, enc_b3, nullptr, buf2);
    kEw1 <<<dim3(512,1,1), b, SMN32 >>>(buf2, erb1_w1, nullptr, nullptr, tmpb);
    kEw2 <<<dim3(512,1,1), b, SMN128>>>(tmpb, erb1_w2, nullptr, buf2, buf2);
    kEw1 <<<dim3(512,1,1), b, SMN32 >>>(buf2, erb2_w1, nullptr, nullptr, tmpb);
    kEw2R<<<dim3(512,1,1), b, SMN128>>>(tmpb, erb2_w2, nullptr, buf2, fptr);

    // ---- VQ (fp32, exact) ----
    emb_prep<<<512,128>>>(emb, embT, ehalf);
    vq_kernel<<<2048,256>>>(fptr, emb, embT, ehalf, qptr);

    // ---- decoder ----
    kDec <<<dim3(512,1,1), b, SMN128>>>(qptr, dec_w, dec_b, nullptr, buf1);
    kDw1 <<<dim3(512,1,1), b, SMN32 >>>(buf1, drb1_w1, nullptr, nullptr, tmpb);
    kDw2 <<<dim3(512,1,1), b, SMN128>>>(tmpb, drb1_w2, nullptr, buf1, buf1);
    kDw1 <<<dim3(512,1,1), b, SMN32 >>>(buf1, drb2_w1, nullptr, nullptr, tmpb);
    kDw2R<<<dim3(512,1,1), b, SMN128>>>(tmpb, drb2_w2, nullptr, buf1, buf2);
    kDt1 <<<dim3(512,1,4), b, SMN64 >>>(buf2, dt1_w, dt1_b, nullptr, buf0);

    dt2_kernel<<<dim3(1024,1,4),b>>>(buf0, dt2_w, dt2_b, out);
}

// round 5
// speedup vs baseline: 1.9718x; 1.0277x over previous
#include <cuda_runtime.h>
#include <cstdint>

// ======================= device scratch (no cudaMalloc allowed) =======================
__device__ float g_buf0[16*128*128*64];   // enc1 out / dt1 out (64 MB)
__device__ float g_buf1[16*64*64*128];    // enc2 out / decoder work (32 MB)
__device__ float g_buf2[16*64*64*128];    // enc3 out / res work / y_mid
__device__ float g_tmpb[16*64*64*32];     // residual mid
__device__ float g_fbuf[16*64*64*128];    // fallback f
__device__ float g_qbuf[16*64*64*128];    // fallback q
__device__ float g_embT[128*512];         // transposed codebook
__device__ float g_ehalf[512];            // 0.5*||e||^2

__device__ __forceinline__ uint32_t f2tf32(float x) {
    uint32_t r; asm("cvt.rna.tf32.f32 %0, %1;" : "=r"(r) : "f"(x)); return r;
}
__device__ __forceinline__ void mma_tf32(float* d, const uint32_t* a, const uint32_t* b) {
    asm volatile(
        "mma.sync.aligned.m16n8k8.row.col.f32.tf32.tf32.f32 "
        "{%0,%1,%2,%3}, {%4,%5,%6,%7}, {%8,%9}, {%0,%1,%2,%3};"
        : "+f"(d[0]), "+f"(d[1]), "+f"(d[2]), "+f"(d[3])
        : "r"(a[0]), "r"(a[1]), "r"(a[2]), "r"(a[3]), "r"(b[0]), "r"(b[1]));
}

// ======================= fp32 tiled implicit-GEMM conv (enc1 only) =======================
template<int BM,int BN,int BK,int TM,int TN,
         int CIN,int COUT,int KH,int KW,int STRIDE,int PAD,
         int INH,int INW,int NB,
         bool RELU_IN,bool HAS_BIAS,bool ADD,bool RELU_OUT,bool TRANS>
__global__ void __launch_bounds__(256)
conv_gemm(const float* __restrict__ in, const float* __restrict__ wgt,
          const float* __restrict__ bias, const float* __restrict__ addsrc,
          float* __restrict__ out)
{
    constexpr int MH = TRANS ? INH : INH / STRIDE;
    constexpr int MW = TRANS ? INW : INW / STRIDE;
    constexpr int K  = TRANS ? 4*CIN : KH*KW*CIN;
    constexpr int THREADS = (BM/TM)*(BN/TN);
    static_assert(THREADS == 256, "block must be 256 threads");

    __shared__ __align__(16) float As[BK][BM+4];
    __shared__ __align__(16) float Bs[BK][BN];

    const int tid = threadIdx.x;
    const int m0  = blockIdx.x * BM;
    const int n0  = blockIdx.y * BN;
    const int py  = TRANS ? (int)(blockIdx.z >> 1) : 0;
    const int px  = TRANS ? (int)(blockIdx.z & 1)  : 0;

    const int tcol = tid % (BN/TN);
    const int trow = tid / (BN/TN);

    float acc[TM][TN];
    #pragma unroll
    for (int i = 0; i < TM; i++)
        #pragma unroll
        for (int j = 0; j < TN; j++) acc[i][j] = 0.f;

    for (int k0 = 0; k0 < K; k0 += BK) {
        #pragma unroll
        for (int i = 0; i < (BM*BK)/THREADS; i++) {
            int l = tid + i*THREADS;
            int mloc = l / BK, kloc = l % BK;
            int m = m0 + mloc;
            int k = k0 + kloc;
            int mx = m % MW; int t = m / MW; int my = t % MH; int n = t / MH;
            float v = 0.f;
            if (TRANS) {
                int ci = k % CIN; int ab = k / CIN;
                int bb = ab & 1, aa = ab >> 1;
                int iy = my + py + aa - 1;
                int ix = mx + px + bb - 1;
                if (iy >= 0 && iy < INH && ix >= 0 && ix < INW)
                    v = in[((n*INH + iy)*INW + ix)*CIN + ci];
            } else {
                int ci = k % CIN; int r = k / CIN;
                int kw = r % KW, kh = r / KW;
                int iy = my*STRIDE - PAD + kh;
                int ix = mx*STRIDE - PAD + kw;
                if (iy >= 0 && iy < INH && ix >= 0 && ix < INW)
                    v = in[((n*INH + iy)*INW + ix)*CIN + ci];
            }
            if (RELU_IN) v = fmaxf(v, 0.f);
            As[kloc][mloc] = v;
        }
        #pragma unroll
        for (int i = 0; i < (BK*BN)/THREADS; i++) {
            int l = tid + i*THREADS;
            int kloc = l / BN, nloc = l % BN;
            int k = k0 + kloc;
            float v;
            if (TRANS) {
                int ci = k % CIN; int ab = k / CIN;
                int bb = ab & 1, aa = ab >> 1;
                int widx = ((2*aa + py)*KW + (2*bb + px))*CIN + ci;
                v = wgt[widx*COUT + n0 + nloc];
            } else {
                v = wgt[k*COUT + n0 + nloc];
            }
            Bs[kloc][nloc] = v;
        }
        __syncthreads();
        #pragma unroll
        for (int kk = 0; kk < BK; kk++) {
            float ra[TM], rb[TN];
            #pragma unroll
            for (int i = 0; i < TM; i += 4) {
                float4 t4 = *reinterpret_cast<const float4*>(&As[kk][trow*TM + i]);
                ra[i]=t4.x; ra[i+1]=t4.y; ra[i+2]=t4.z; ra[i+3]=t4.w;
            }
            #pragma unroll
            for (int j = 0; j < TN; j += 4) {
                float4 t4 = *reinterpret_cast<const float4*>(&Bs[kk][tcol*TN + j]);
                rb[j]=t4.x; rb[j+1]=t4.y; rb[j+2]=t4.z; rb[j+3]=t4.w;
            }
            #pragma unroll
            for (int i = 0; i < TM; i++)
                #pragma unroll
                for (int j = 0; j < TN; j++)
                    acc[i][j] += ra[i]*rb[j];
        }
        __syncthreads();
    }
    #pragma unroll
    for (int i = 0; i < TM; i++) {
        int m = m0 + trow*TM + i;
        int obase;
        if (TRANS) {
            int mx = m % MW; int t = m / MW; int my = t % MH; int n = t / MH;
            obase = ((n*(2*INH) + 2*my + py)*(2*INW) + 2*mx + px)*COUT;
        } else {
            obase = m*COUT;
        }
        #pragma unroll
        for (int j = 0; j < TN; j++) {
            int c = n0 + tcol*TN + j;
            float v = acc[i][j];
            if (HAS_BIAS) v += bias[c];
            if (ADD)      v += addsrc[obase + c];
            if (RELU_OUT) v = fmaxf(v, 0.f);
            out[obase + c] = v;
        }
    }
}

// ====== tf32 mma.sync implicit-GEMM conv, register-staged, pre-converted smem ======
// Tiles are loaded gmem->regs (overlapping compute of previous tile), then converted
// to tf32 hi (and lo for SPLIT=3) ONCE at smem store. Inner loop is pure LDS + MMA.
// SPLIT=1: single-pass tf32 (decoder). SPLIT=3: 3xTF32 (encoder, ~fp32 precision):
//   D += a_lo*b_hi + a_hi*b_lo + a_hi*b_hi.
template<int CIN,int COUT,int KH,int KW,int STRIDE,int PAD,int INH,int INW,
         bool RELU_IN,bool HAS_BIAS,bool ADD,bool RELU_OUT,bool TRANS,int SPLIT>
__global__ void __launch_bounds__(256)
mma_conv3(const float* __restrict__ in, const float* __restrict__ wgt,
          const float* __restrict__ bias, const float* __restrict__ addsrc,
          float* __restrict__ out)
{
    constexpr int MH = TRANS ? INH : INH / STRIDE;
    constexpr int MW = TRANS ? INW : INW / STRIDE;
    constexpr int K  = TRANS ? 4*CIN : KH*KW*CIN;
    constexpr int BM = 128, BK = 32, BN = COUT;
    constexpr int S  = K / BK;
    constexpr int WARPS_N = (BN >= 64) ? 2 : 1;
    constexpr int WARPS_M = 8 / WARPS_N;
    constexpr int WM = BM / WARPS_M;
    constexpr int WN = BN / WARPS_N;
    constexpr int MF = WM / 16;
    constexpr int NF = WN / 8;
    constexpr int ASTR = BK + 4;       // 36
    constexpr int BSTR = BN + 8;
    constexpr int A_WORDS = BM*ASTR;
    constexpr int B_WORDS = BK*BSTR;
    constexpr int NBREG = (BK*BN)/(4*256);   // float4 B regs per thread (1,2,4)

    extern __shared__ __align__(16) uint32_t smem[];
    uint32_t* AsH = smem;
    uint32_t* AsL = AsH + A_WORDS;                      // only used if SPLIT==3
    uint32_t* BsH = AsH + (SPLIT==3 ? 2 : 1)*A_WORDS;
    uint32_t* BsL = BsH + B_WORDS;

    const int tid  = threadIdx.x;
    const int wid  = tid >> 5;
    const int lane = tid & 31;
    const int m0   = blockIdx.x * BM;
    const int py   = TRANS ? (int)(blockIdx.z >> 1) : 0;
    const int px   = TRANS ? (int)(blockIdx.z & 1)  : 0;
    const int wm   = wid / WARPS_N;
    const int wn   = wid % WARPS_N;
    const int lr   = lane >> 2;
    const int lc   = lane & 3;

    float acc[MF][NF][4];
    #pragma unroll
    for (int i = 0; i < MF; i++)
        #pragma unroll
        for (int j = 0; j < NF; j++)
            #pragma unroll
            for (int r = 0; r < 4; r++) acc[i][j][r] = 0.f;

    float4 aR[4];
    float4 bR[NBREG];

    // ---- gmem -> regs loader for k-slab s ----
    auto load_regs = [&](int s) {
        const int k0 = s * BK;
        #pragma unroll
        for (int it = 0; it < 4; it++) {
            int l = tid + it*256;
            int m = l >> 3, kq = l & 7;
            int k = k0 + kq*4;
            int mg = m0 + m;
            int mx = mg % MW; int t = mg / MW; int my = t % MH; int n = t / MH;
            int iy, ix, ci;
            if (TRANS) {
                ci = k % CIN; int ab = k / CIN;
                int bb = ab & 1, aa = ab >> 1;
                iy = my + py + aa - 1;
                ix = mx + px + bb - 1;
            } else {
                ci = k % CIN; int r = k / CIN;
                int kw = r % KW, kh = r / KW;
                iy = my*STRIDE - PAD + kh;
                ix = mx*STRIDE - PAD + kw;
            }
            if (iy >= 0 && iy < INH && ix >= 0 && ix < INW)
                aR[it] = *reinterpret_cast<const float4*>(&in[((n*INH + iy)*INW + ix)*CIN + ci]);
            else
                aR[it] = make_float4(0.f,0.f,0.f,0.f);
        }
        #pragma unroll
        for (int it = 0; it < NBREG; it++) {
            int l = tid + it*256;
            int co = (l % (BN/4))*4;
            int kk = l / (BN/4);
            int k = k0 + kk;
            if (TRANS) {
                int ci = k % CIN; int ab = k / CIN;
                int bb = ab & 1, aa = ab >> 1;
                int widx = ((2*aa + py)*KW + (2*bb + px))*CIN + ci;
                bR[it] = *reinterpret_cast<const float4*>(&wgt[widx*COUT + co]);
            } else {
                bR[it] = *reinterpret_cast<const float4*>(&wgt[k*COUT + co]);
            }
        }
    };

    // ---- regs -> smem with tf32 conversion (hi/lo) ----
    auto store_regs = [&]() {
        #pragma unroll
        for (int it = 0; it < 4; it++) {
            int l = tid + it*256;
            int m = l >> 3, kq = l & 7;
            float4 v = aR[it];
            if (RELU_IN) {
                v.x = fmaxf(v.x, 0.f); v.y = fmaxf(v.y, 0.f);
                v.z = fmaxf(v.z, 0.f); v.w = fmaxf(v.w, 0.f);
            }
            uint4 h;
            h.x = f2tf32(v.x); h.y = f2tf32(v.y); h.z = f2tf32(v.z); h.w = f2tf32(v.w);
            *reinterpret_cast<uint4*>(&AsH[m*ASTR + kq*4]) = h;
            if (SPLIT == 3) {
                uint4 lo;
                lo.x = f2tf32(v.x - __uint_as_float(h.x));
                lo.y = f2tf32(v.y - __uint_as_float(h.y));
                lo.z = f2tf32(v.z - __uint_as_float(h.z));
                lo.w = f2tf32(v.w - __uint_as_float(h.w));
                *reinterpret_cast<uint4*>(&AsL[m*ASTR + kq*4]) = lo;
            }
        }
        #pragma unroll
        for (int it = 0; it < NBREG; it++) {
            int l = tid + it*256;
            int co = (l % (BN/4))*4;
            int kk = l / (BN/4);
            float4 w = bR[it];
            uint4 h;
            h.x = f2tf32(w.x); h.y = f2tf32(w.y); h.z = f2tf32(w.z); h.w = f2tf32(w.w);
            *reinterpret_cast<uint4*>(&BsH[kk*BSTR + co]) = h;
            if (SPLIT == 3) {
                uint4 lo;
                lo.x = f2tf32(w.x - __uint_as_float(h.x));
                lo.y = f2tf32(w.y - __uint_as_float(h.y));
                lo.z = f2tf32(w.z - __uint_as_float(h.z));
                lo.w = f2tf32(w.w - __uint_as_float(h.w));
                *reinterpret_cast<uint4*>(&BsL[kk*BSTR + co]) = lo;
            }
        }
    };

    load_regs(0);
    for (int s = 0; s < S; s++) {
        if (s > 0) __syncthreads();     // previous tile fully consumed
        store_regs();
        __syncthreads();
        if (s + 1 < S) load_regs(s + 1);  // overlap next loads with compute
        #pragma unroll
        for (int ks = 0; ks < BK; ks += 8) {
            uint32_t ah[MF][4], al[MF][4];
            #pragma unroll
            for (int i = 0; i < MF; i++) {
                int r = wm*WM + i*16 + lr;
                ah[i][0] = AsH[(r    )*ASTR + ks + lc];
                ah[i][1] = AsH[(r + 8)*ASTR + ks + lc];
                ah[i][2] = AsH[(r    )*ASTR + ks + lc + 4];
                ah[i][3] = AsH[(r + 8)*ASTR + ks + lc + 4];
                if (SPLIT == 3) {
                    al[i][0] = AsL[(r    )*ASTR + ks + lc];
                    al[i][1] = AsL[(r + 8)*ASTR + ks + lc];
                    al[i][2] = AsL[(r    )*ASTR + ks + lc + 4];
                    al[i][3] = AsL[(r + 8)*ASTR + ks + lc + 4];
                }
            }
            #pragma unroll
            for (int j = 0; j < NF; j++) {
                int c = wn*WN + j*8 + lr;
                uint32_t bh[2], bl[2];
                bh[0] = BsH[(ks + lc    )*BSTR + c];
                bh[1] = BsH[(ks + lc + 4)*BSTR + c];
                if (SPLIT == 3) {
                    bl[0] = BsL[(ks + lc    )*BSTR + c];
                    bl[1] = BsL[(ks + lc + 4)*BSTR + c];
                }
                #pragma unroll
                for (int i = 0; i < MF; i++) {
                    if (SPLIT == 3) {
                        mma_tf32(acc[i][j], al[i], bh);
                        mma_tf32(acc[i][j], ah[i], bl);
                    }
                    mma_tf32(acc[i][j], ah[i], bh);
                }
            }
        }
    }

    // ---- epilogue: fuse bias/add/relu, float2 stores ----
    #pragma unroll
    for (int i = 0; i < MF; i++) {
        int r0 = m0 + wm*WM + i*16 + lr;
        #pragma unroll
        for (int half = 0; half < 2; half++) {
            int mg = r0 + half*8;
            int obase;
            if (TRANS) {
                int mx = mg % MW; int t = mg / MW; int my = t % MH; int n = t / MH;
                obase = ((n*(2*INH) + 2*my + py)*(2*INW) + 2*mx + px)*COUT;
            } else {
                obase = mg*COUT;
            }
            #pragma unroll
            for (int j = 0; j < NF; j++) {
                int c = wn*WN + j*8 + 2*lc;
                float v0 = acc[i][j][half*2 + 0];
                float v1 = acc[i][j][half*2 + 1];
                if (HAS_BIAS) {
                    float2 bv = *reinterpret_cast<const float2*>(&bias[c]);
                    v0 += bv.x; v1 += bv.y;
                }
                if (ADD) {
                    float2 av = *reinterpret_cast<const float2*>(&addsrc[obase + c]);
                    v0 += av.x; v1 += av.y;
                }
                if (RELU_OUT) { v0 = fmaxf(v0, 0.f); v1 = fmaxf(v1, 0.f); }
                float2 ov; ov.x = v0; ov.y = v1;
                *reinterpret_cast<float2*>(&out[obase + c]) = ov;
            }
        }
    }
}

// ======================= codebook prep =======================
__global__ void emb_prep(const float* __restrict__ emb,
                         float* __restrict__ embT, float* __restrict__ ehalf)
{
    int c = blockIdx.x;
    int k = threadIdx.x;
    float v = emb[c*128 + k];
    embT[k*512 + c] = v;
    float s = v*v;
    #pragma unroll
    for (int o = 16; o; o >>= 1) s += __shfl_xor_sync(0xffffffffu, s, o);
    __shared__ float red[4];
    if ((k & 31) == 0) red[k >> 5] = s;
    __syncthreads();
    if (k == 0) ehalf[c] = 0.5f*(red[0]+red[1]+red[2]+red[3]);
}

// ======================= VQ =======================
__global__ void __launch_bounds__(256)
vq_kernel(const float* __restrict__ f, const float* __restrict__ emb,
          const float* __restrict__ embT, const float* __restrict__ ehalf,
          float* __restrict__ q)
{
    __shared__ __align__(16) float As[16][36];
    __shared__ __align__(16) float Bs[16][512];
    __shared__ float bv[32][17];
    __shared__ int   bi[32][17];
    __shared__ int   rowIdx[32];

    const int tid = threadIdx.x;
    const int tx  = tid & 15;
    const int ty  = tid >> 4;
    const int m0  = blockIdx.x * 32;

    float acc0[32], acc1[32];
    #pragma unroll
    for (int j = 0; j < 32; j++) { acc0[j] = 0.f; acc1[j] = 0.f; }

    for (int k0 = 0; k0 < 128; k0 += 16) {
        #pragma unroll
        for (int i = 0; i < 2; i++) {
            int l = tid + i*256;
            As[l & 15][l >> 4] = f[(m0 + (l >> 4))*128 + k0 + (l & 15)];
        }
        #pragma unroll
        for (int i = 0; i < 32; i++) {
            int l = tid + i*256;
            Bs[l >> 9][l & 511] = embT[(k0 + (l >> 9))*512 + (l & 511)];
        }
        __syncthreads();
        #pragma unroll
        for (int kk = 0; kk < 16; kk++) {
            float ra0 = As[kk][ty*2], ra1 = As[kk][ty*2 + 1];
            #pragma unroll
            for (int j = 0; j < 32; j++) {
                float rb = Bs[kk][tx + (j << 4)];
                acc0[j] += ra0*rb; acc1[j] += ra1*rb;
            }
        }
        __syncthreads();
    }
    {
        float b0 = -3.4e38f, b1 = -3.4e38f; int i0 = 0, i1 = 0;
        #pragma unroll
        for (int j = 0; j < 32; j++) {
            int code = tx + (j << 4);
            float h = __ldg(&ehalf[code]);
            float s0 = acc0[j] - h;
            float s1 = acc1[j] - h;
            if (s0 > b0 || (s0 == b0 && code < i0)) { b0 = s0; i0 = code; }
            if (s1 > b1 || (s1 == b1 && code < i1)) { b1 = s1; i1 = code; }
        }
        bv[ty*2][tx] = b0;  bi[ty*2][tx] = i0;
        bv[ty*2+1][tx] = b1; bi[ty*2+1][tx] = i1;
    }
    __syncthreads();
    if (tid < 32) {
        float best = -3.4e38f; int bidx = 0;
        #pragma unroll
        for (int t2 = 0; t2 < 16; t2++) {
            float s = bv[tid][t2]; int c = bi[tid][t2];
            if (s > best || (s == best && c < bidx)) { best = s; bidx = c; }
        }
        rowIdx[tid] = bidx;
    }
    __syncthreads();
    for (int l = tid; l < 32*128; l += 256) {
        int r = l >> 7, j = l & 127;
        q[(m0 + r)*128 + j] = emb[rowIdx[r]*128 + j];
    }
}

// ======================= dt2: 4x4 s2 tconv 64->3, direct =======================
__global__ void __launch_bounds__(256)
dt2_kernel(const float* __restrict__ in,
           const float* __restrict__ wgt,
           const float* __restrict__ bias,
           float* __restrict__ out)
{
    __shared__ float ws[4*4*64*3];
    for (int l = threadIdx.x; l < 3072; l += 256) ws[l] = wgt[l];
    __syncthreads();

    const int py = blockIdx.z >> 1, px = blockIdx.z & 1;
    const int m = blockIdx.x * 256 + threadIdx.x;
    const int xq = m & 127; int t = m >> 7; const int yq = t & 127; const int n = t >> 7;

    float a0 = __ldg(&bias[0]), a1 = __ldg(&bias[1]), a2 = __ldg(&bias[2]);
    #pragma unroll
    for (int aa = 0; aa < 2; aa++) {
        #pragma unroll
        for (int bb = 0; bb < 2; bb++) {
            int iy = yq + py + aa - 1;
            int ix = xq + px + bb - 1;
            if (iy < 0 || iy >= 128 || ix < 0 || ix >= 128) continue;
            const float* ip = in + ((n*128 + iy)*128 + ix)*64;
            const float* wp = ws + ((2*aa + py)*4 + (2*bb + px))*64*3;
            #pragma unroll
            for (int ci = 0; ci < 64; ci += 4) {
                float4 v = *reinterpret_cast<const float4*>(ip + ci);
                const float* w0 = wp + ci*3;
                a0 += v.x*w0[0];  a1 += v.x*w0[1];  a2 += v.x*w0[2];
                a0 += v.y*w0[3];  a1 += v.y*w0[4];  a2 += v.y*w0[5];
                a0 += v.z*w0[6];  a1 += v.z*w0[7];  a2 += v.z*w0[8];
                a0 += v.w*w0[9];  a1 += v.w*w0[10]; a2 += v.w*w0[11];
            }
        }
    }
    const int oy = 2*yq + py, ox = 2*xq + px;
    float* op = out + ((n*256 + oy)*256 + ox)*3;
    op[0] = a0; op[1] = a1; op[2] = a2;
}

// ======================= host launcher =======================
extern "C" void kernel_launch(void* const* d_in, const int* in_sizes, int n_in,
                              void* d_out, int out_size)
{
    (void)in_sizes; (void)n_in;
    const float* x       = (const float*)d_in[0];
    const float* emb     = (const float*)d_in[1];
    const float* enc_w1  = (const float*)d_in[2];
    const float* enc_b1  = (const float*)d_in[3];
    const float* enc_w2  = (const float*)d_in[4];
    const float* enc_b2  = (const float*)d_in[5];
    const float* enc_w3  = (const float*)d_in[6];
    const float* enc_b3  = (const float*)d_in[7];
    const float* erb1_w1 = (const float*)d_in[8];
    const float* erb1_w2 = (const float*)d_in[9];
    const float* erb2_w1 = (const float*)d_in[10];
    const float* erb2_w2 = (const float*)d_in[11];
    const float* dec_w   = (const float*)d_in[12];
    const float* dec_b   = (const float*)d_in[13];
    const float* drb1_w1 = (const float*)d_in[14];
    const float* drb1_w2 = (const float*)d_in[15];
    const float* drb2_w1 = (const float*)d_in[16];
    const float* drb2_w2 = (const float*)d_in[17];
    const float* dt1_w   = (const float*)d_in[18];
    const float* dt1_b   = (const float*)d_in[19];
    const float* dt2_w   = (const float*)d_in[20];
    const float* dt2_b   = (const float*)d_in[21];

    float* out = (float*)d_out;
    const int YS = 16*256*256*3;
    const int FS = 16*64*64*128;

    float *buf0,*buf1,*buf2,*tmpb,*embT,*ehalf,*fb,*qb;
    cudaGetSymbolAddress((void**)&buf0,  g_buf0);
    cudaGetSymbolAddress((void**)&buf1,  g_buf1);
    cudaGetSymbolAddress((void**)&buf2,  g_buf2);
    cudaGetSymbolAddress((void**)&tmpb,  g_tmpb);
    cudaGetSymbolAddress((void**)&embT,  g_embT);
    cudaGetSymbolAddress((void**)&ehalf, g_ehalf);
    cudaGetSymbolAddress((void**)&fb,    g_fbuf);
    cudaGetSymbolAddress((void**)&qb,    g_qbuf);

    const bool full = (out_size >= YS + 2*FS);
    float* fptr = full ? (out + YS)      : fb;
    float* qptr = full ? (out + YS + FS) : qb;

    dim3 b(256);

    // smem bytes: (SPLIT==3?2:1)*(128*36) + (SPLIT==3?2:1)*(32*(BN+8)), x4 bytes
    const int SM3_128 = (2*128*36 + 2*32*136)*4;  // 71680
    const int SM3_32  = (2*128*36 + 2*32*40)*4;   // 47104
    const int SM1_128 = (128*36 + 32*136)*4;      // 35840
    const int SM1_64  = (128*36 + 32*72)*4;       // 27648
    const int SM1_32  = (128*36 + 32*40)*4;       // 23552

    // ---- encoder (3xTF32) ----
    auto kEnc2 = mma_conv3<64,128,4,4,2,1, 128,128, false,true,false,true,false,3>;
    auto kEnc3 = mma_conv3<128,128,3,3,1,1, 64,64, false,true,false,false,false,3>;
    auto kEw1  = mma_conv3<128,32, 3,3,1,1, 64,64, true,false,false,true,false,3>;
    auto kEw2  = mma_conv3<32,128, 1,1,1,0, 64,64, false,false,true,false,false,3>;
    auto kEw2R = mma_conv3<32,128, 1,1,1,0, 64,64, false,false,true,true,false,3>;
    // ---- decoder (single-pass tf32) ----
    auto kDec  = mma_conv3<128,128,3,3,1,1, 64,64, false,true,false,false,false,1>;
    auto kDw1  = mma_conv3<128,32, 3,3,1,1, 64,64, true,false,false,true,false,1>;
    auto kDw2  = mma_conv3<32,128, 1,1,1,0, 64,64, false,false,true,false,false,1>;
    auto kDw2R = mma_conv3<32,128, 1,1,1,0, 64,64, false,false,true,true,false,1>;
    auto kDt1  = mma_conv3<128,64, 4,4,2,0, 64,64, false,true,false,true,true,1>;

    cudaFuncSetAttribute(kEnc2, cudaFuncAttributeMaxDynamicSharedMemorySize, SM3_128);
    cudaFuncSetAttribute(kEnc3, cudaFuncAttributeMaxDynamicSharedMemorySize, SM3_128);
    cudaFuncSetAttribute(kEw1,  cudaFuncAttributeMaxDynamicSharedMemorySize, SM3_32);
    cudaFuncSetAttribute(kEw2,  cudaFuncAttributeMaxDynamicSharedMemorySize, SM3_128);
    cudaFuncSetAttribute(kEw2R, cudaFuncAttributeMaxDynamicSharedMemorySize, SM3_128);
    cudaFuncSetAttribute(kDec,  cudaFuncAttributeMaxDynamicSharedMemorySize, SM1_128);
    cudaFuncSetAttribute(kDw1,  cudaFuncAttributeMaxDynamicSharedMemorySize, SM1_32);
    cudaFuncSetAttribute(kDw2,  cudaFuncAttributeMaxDynamicSharedMemorySize, SM1_128);
    cudaFuncSetAttribute(kDw2R, cudaFuncAttributeMaxDynamicSharedMemorySize, SM1_128);
    cudaFuncSetAttribute(kDt1,  cudaFuncAttributeMaxDynamicSharedMemorySize, SM1_64);

    // ---- encoder ----
    conv_gemm<64,64,16,4,4,  3,64,4,4,2,1, 256,256,16, false,true,false,true,false>
        <<<dim3(4096,1,1),b>>>(x, enc_w1, enc_b1, nullptr, buf0);
    kEnc2<<<dim3(512,1,1), b, SM3_128>>>(buf0, enc_w2, enc_b2, nullptr, buf1);
    kEnc3<<<dim3(512,1,1), b, SM3_128>>>(buf1, enc_w3, enc_b3, nullptr, buf2);
    kEw1 <<<dim3(512,1,1), b, SM3_32 >>>(buf2, erb1_w1, nullptr, nullptr, tmpb);
    kEw2 <<<dim3(512,1,1), b, SM3_128>>>(tmpb, erb1_w2, nullptr, buf2, buf2);
    kEw1 <<<dim3(512,1,1), b, SM3_32 >>>(buf2, erb2_w1, nullptr, nullptr, tmpb);
    kEw2R<<<dim3(512,1,1), b, SM3_128>>>(tmpb, erb2_w2, nullptr, buf2, fptr);

    // ---- VQ (fp32, exact) ----
    emb_prep<<<512,128>>>(emb, embT, ehalf);
    vq_kernel<<<2048,256>>>(fptr, emb, embT, ehalf, qptr);

    // ---- decoder ----
    kDec <<<dim3(512,1,1), b, SM1_128>>>(qptr, dec_w, dec_b, nullptr, buf1);
    kDw1 <<<dim3(512,1,1), b, SM1_32 >>>(buf1, drb1_w1, nullptr, nullptr, tmpb);
    kDw2 <<<dim3(512,1,1), b, SM1_128>>>(tmpb, drb1_w2, nullptr, buf1, buf1);
    kDw1 <<<dim3(512,1,1), b, SM1_32 >>>(buf1, drb2_w1, nullptr, nullptr, tmpb);
    kDw2R<<<dim3(512,1,1), b, SM1_128>>>(tmpb, drb2_w2, nullptr, buf1, buf2);
    kDt1 <<<dim3(512,1,4), b, SM1_64 >>>(buf2, dt1_w, dt1_b, nullptr, buf0);

    dt2_kernel<<<dim3(1024,1,4),b>>>(buf0, dt2_w, dt2_b, out);
}

// round 7
// speedup vs baseline: 2.0696x; 1.0496x over previous
#include <cuda_runtime.h>
#include <cstdint>

// ======================= device scratch (no cudaMalloc allowed) =======================
__device__ float g_buf0[16*128*128*64];   // enc1 out / dt1 out (64 MB)
__device__ float g_buf1[16*64*64*128];    // enc2 out / decoder work (32 MB)
__device__ float g_buf2[16*64*64*128];    // enc3 out / res work / y_mid
__device__ float g_tmpb[16*64*64*32];     // residual mid
__device__ float g_fbuf[16*64*64*128];    // fallback f
__device__ float g_qbuf[16*64*64*128];    // fallback q
__device__ float g_embT[128*512];         // transposed codebook
__device__ float g_ehalf[512];            // 0.5*||e||^2

__device__ __forceinline__ uint32_t f2tf32(float x) {
    uint32_t r; asm("cvt.rna.tf32.f32 %0, %1;" : "=r"(r) : "f"(x)); return r;
}
__device__ __forceinline__ void mma_tf32(float* d, const uint32_t* a, const uint32_t* b) {
    asm volatile(
        "mma.sync.aligned.m16n8k8.row.col.f32.tf32.tf32.f32 "
        "{%0,%1,%2,%3}, {%4,%5,%6,%7}, {%8,%9}, {%0,%1,%2,%3};"
        : "+f"(d[0]), "+f"(d[1]), "+f"(d[2]), "+f"(d[3])
        : "r"(a[0]), "r"(a[1]), "r"(a[2]), "r"(a[3]), "r"(b[0]), "r"(b[1]));
}

// ======================= fp32 tiled implicit-GEMM conv (enc1 only) =======================
template<int BM,int BN,int BK,int TM,int TN,
         int CIN,int COUT,int KH,int KW,int STRIDE,int PAD,
         int INH,int INW,int NB,
         bool RELU_IN,bool HAS_BIAS,bool ADD,bool RELU_OUT,bool TRANS>
__global__ void __launch_bounds__(256)
conv_gemm(const float* __restrict__ in, const float* __restrict__ wgt,
          const float* __restrict__ bias, const float* __restrict__ addsrc,
          float* __restrict__ out)
{
    constexpr int MH = TRANS ? INH : INH / STRIDE;
    constexpr int MW = TRANS ? INW : INW / STRIDE;
    constexpr int K  = TRANS ? 4*CIN : KH*KW*CIN;
    constexpr int THREADS = (BM/TM)*(BN/TN);
    static_assert(THREADS == 256, "block must be 256 threads");

    __shared__ __align__(16) float As[BK][BM+4];
    __shared__ __align__(16) float Bs[BK][BN];

    const int tid = threadIdx.x;
    const int m0  = blockIdx.x * BM;
    const int n0  = blockIdx.y * BN;
    const int py  = TRANS ? (int)(blockIdx.z >> 1) : 0;
    const int px  = TRANS ? (int)(blockIdx.z & 1)  : 0;

    const int tcol = tid % (BN/TN);
    const int trow = tid / (BN/TN);

    float acc[TM][TN];
    #pragma unroll
    for (int i = 0; i < TM; i++)
        #pragma unroll
        for (int j = 0; j < TN; j++) acc[i][j] = 0.f;

    for (int k0 = 0; k0 < K; k0 += BK) {
        #pragma unroll
        for (int i = 0; i < (BM*BK)/THREADS; i++) {
            int l = tid + i*THREADS;
            int mloc = l / BK, kloc = l % BK;
            int m = m0 + mloc;
            int k = k0 + kloc;
            int mx = m % MW; int t = m / MW; int my = t % MH; int n = t / MH;
            float v = 0.f;
            if (TRANS) {
                int ci = k % CIN; int ab = k / CIN;
                int bb = ab & 1, aa = ab >> 1;
                int iy = my + py + aa - 1;
                int ix = mx + px + bb - 1;
                if (iy >= 0 && iy < INH && ix >= 0 && ix < INW)
                    v = in[((n*INH + iy)*INW + ix)*CIN + ci];
            } else {
                int ci = k % CIN; int r = k / CIN;
                int kw = r % KW, kh = r / KW;
                int iy = my*STRIDE - PAD + kh;
                int ix = mx*STRIDE - PAD + kw;
                if (iy >= 0 && iy < INH && ix >= 0 && ix < INW)
                    v = in[((n*INH + iy)*INW + ix)*CIN + ci];
            }
            if (RELU_IN) v = fmaxf(v, 0.f);
            As[kloc][mloc] = v;
        }
        #pragma unroll
        for (int i = 0; i < (BK*BN)/THREADS; i++) {
            int l = tid + i*THREADS;
            int kloc = l / BN, nloc = l % BN;
            int k = k0 + kloc;
            float v;
            if (TRANS) {
                int ci = k % CIN; int ab = k / CIN;
                int bb = ab & 1, aa = ab >> 1;
                int widx = ((2*aa + py)*KW + (2*bb + px))*CIN + ci;
                v = wgt[widx*COUT + n0 + nloc];
            } else {
                v = wgt[k*COUT + n0 + nloc];
            }
            Bs[kloc][nloc] = v;
        }
        __syncthreads();
        #pragma unroll
        for (int kk = 0; kk < BK; kk++) {
            float ra[TM], rb[TN];
            #pragma unroll
            for (int i = 0; i < TM; i += 4) {
                float4 t4 = *reinterpret_cast<const float4*>(&As[kk][trow*TM + i]);
                ra[i]=t4.x; ra[i+1]=t4.y; ra[i+2]=t4.z; ra[i+3]=t4.w;
            }
            #pragma unroll
            for (int j = 0; j < TN; j += 4) {
                float4 t4 = *reinterpret_cast<const float4*>(&Bs[kk][tcol*TN + j]);
                rb[j]=t4.x; rb[j+1]=t4.y; rb[j+2]=t4.z; rb[j+3]=t4.w;
            }
            #pragma unroll
            for (int i = 0; i < TM; i++)
                #pragma unroll
                for (int j = 0; j < TN; j++)
                    acc[i][j] += ra[i]*rb[j];
        }
        __syncthreads();
    }
    #pragma unroll
    for (int i = 0; i < TM; i++) {
        int m = m0 + trow*TM + i;
        int obase;
        if (TRANS) {
            int mx = m % MW; int t = m / MW; int my = t % MH; int n = t / MH;
            obase = ((n*(2*INH) + 2*my + py)*(2*INW) + 2*mx + px)*COUT;
        } else {
            obase = m*COUT;
        }
        #pragma unroll
        for (int j = 0; j < TN; j++) {
            int c = n0 + tcol*TN + j;
            float v = acc[i][j];
            if (HAS_BIAS) v += bias[c];
            if (ADD)      v += addsrc[obase + c];
            if (RELU_OUT) v = fmaxf(v, 0.f);
            out[obase + c] = v;
        }
    }
}

// ====== tf32 mma.sync implicit-GEMM conv, register-staged, pre-converted smem ======
// DB=1: ping-pong smem buffers, ONE sync per k-slab. DB=0: single buffer, two syncs.
// SPLIT=3: 3xTF32 hi/lo (encoder, ~fp32 precision); SPLIT=1: plain tf32 (decoder).
template<int CIN,int COUT,int KH,int KW,int STRIDE,int PAD,int INH,int INW,
         bool RELU_IN,bool HAS_BIAS,bool ADD,bool RELU_OUT,bool TRANS,int SPLIT,int DB>
__global__ void __launch_bounds__(256)
mma_conv3(const float* __restrict__ in, const float* __restrict__ wgt,
          const float* __restrict__ bias, const float* __restrict__ addsrc,
          float* __restrict__ out)
{
    constexpr int MH = TRANS ? INH : INH / STRIDE;
    constexpr int MW = TRANS ? INW : INW / STRIDE;
    constexpr int K  = TRANS ? 4*CIN : KH*KW*CIN;
    constexpr int BM = 128, BK = 32, BN = COUT;
    constexpr int S  = K / BK;
    constexpr int WARPS_N = (BN >= 64) ? 2 : 1;
    constexpr int WARPS_M = 8 / WARPS_N;
    constexpr int WM = BM / WARPS_M;
    constexpr int WN = BN / WARPS_N;
    constexpr int MF = WM / 16;
    constexpr int NF = WN / 8;
    constexpr int ASTR = BK + 4;
    constexpr int BSTR = BN + 8;
    constexpr int A_WORDS = BM*ASTR;
    constexpr int B_WORDS = BK*BSTR;
    constexpr int NCOPY = (SPLIT==3 ? 2 : 1);
    constexpr int CSZ = NCOPY*(A_WORDS + B_WORDS);
    constexpr int NBREG = (BK*BN)/(4*256);

    extern __shared__ __align__(16) uint32_t smem[];

    const int tid  = threadIdx.x;
    const int wid  = tid >> 5;
    const int lane = tid & 31;
    const int m0   = blockIdx.x * BM;
    const int py   = TRANS ? (int)(blockIdx.z >> 1) : 0;
    const int px   = TRANS ? (int)(blockIdx.z & 1)  : 0;
    const int wm   = wid / WARPS_N;
    const int wn   = wid % WARPS_N;
    const int lr   = lane >> 2;
    const int lc   = lane & 3;

    float acc[MF][NF][4];
    #pragma unroll
    for (int i = 0; i < MF; i++)
        #pragma unroll
        for (int j = 0; j < NF; j++)
            #pragma unroll
            for (int r = 0; r < 4; r++) acc[i][j][r] = 0.f;

    float4 aR[4];
    float4 bR[NBREG];

    auto load_regs = [&](int s) {
        const int k0 = s * BK;
        #pragma unroll
        for (int it = 0; it < 4; it++) {
            int l = tid + it*256;
            int m = l >> 3, kq = l & 7;
            int k = k0 + kq*4;
            int mg = m0 + m;
            int mx = mg % MW; int t = mg / MW; int my = t % MH; int n = t / MH;
            int iy, ix, ci;
            if (TRANS) {
                ci = k % CIN; int ab = k / CIN;
                int bb = ab & 1, aa = ab >> 1;
                iy = my + py + aa - 1;
                ix = mx + px + bb - 1;
            } else {
                ci = k % CIN; int r = k / CIN;
                int kw = r % KW, kh = r / KW;
                iy = my*STRIDE - PAD + kh;
                ix = mx*STRIDE - PAD + kw;
            }
            if (iy >= 0 && iy < INH && ix >= 0 && ix < INW)
                aR[it] = *reinterpret_cast<const float4*>(&in[((n*INH + iy)*INW + ix)*CIN + ci]);
            else
                aR[it] = make_float4(0.f,0.f,0.f,0.f);
        }
        #pragma unroll
        for (int it = 0; it < NBREG; it++) {
            int l = tid + it*256;
            int co = (l % (BN/4))*4;
            int kk = l / (BN/4);
            int k = k0 + kk;
            if (TRANS) {
                int ci = k % CIN; int ab = k / CIN;
                int bb = ab & 1, aa = ab >> 1;
                int widx = ((2*aa + py)*KW + (2*bb + px))*CIN + ci;
                bR[it] = *reinterpret_cast<const float4*>(&wgt[widx*COUT + co]);
            } else {
                bR[it] = *reinterpret_cast<const float4*>(&wgt[k*COUT + co]);
            }
        }
    };

    auto store_regs = [&](int buf) {
        uint32_t* AsH = smem + buf*CSZ;
        uint32_t* AsL = AsH + A_WORDS;
        uint32_t* BsH = AsH + NCOPY*A_WORDS;
        uint32_t* BsL = BsH + B_WORDS;
        #pragma unroll
        for (int it = 0; it < 4; it++) {
            int l = tid + it*256;
            int m = l >> 3, kq = l & 7;
            float4 v = aR[it];
            if (RELU_IN) {
                v.x = fmaxf(v.x, 0.f); v.y = fmaxf(v.y, 0.f);
                v.z = fmaxf(v.z, 0.f); v.w = fmaxf(v.w, 0.f);
            }
            uint4 h;
            h.x = f2tf32(v.x); h.y = f2tf32(v.y); h.z = f2tf32(v.z); h.w = f2tf32(v.w);
            *reinterpret_cast<uint4*>(&AsH[m*ASTR + kq*4]) = h;
            if (SPLIT == 3) {
                uint4 lo;
                lo.x = f2tf32(v.x - __uint_as_float(h.x));
                lo.y = f2tf32(v.y - __uint_as_float(h.y));
                lo.z = f2tf32(v.z - __uint_as_float(h.z));
                lo.w = f2tf32(v.w - __uint_as_float(h.w));
                *reinterpret_cast<uint4*>(&AsL[m*ASTR + kq*4]) = lo;
            }
        }
        #pragma unroll
        for (int it = 0; it < NBREG; it++) {
            int l = tid + it*256;
            int co = (l % (BN/4))*4;
            int kk = l / (BN/4);
            float4 w = bR[it];
            uint4 h;
            h.x = f2tf32(w.x); h.y = f2tf32(w.y); h.z = f2tf32(w.z); h.w = f2tf32(w.w);
            *reinterpret_cast<uint4*>(&BsH[kk*BSTR + co]) = h;
            if (SPLIT == 3) {
                uint4 lo;
                lo.x = f2tf32(w.x - __uint_as_float(h.x));
                lo.y = f2tf32(w.y - __uint_as_float(h.y));
                lo.z = f2tf32(w.z - __uint_as_float(h.z));
                lo.w = f2tf32(w.w - __uint_as_float(h.w));
                *reinterpret_cast<uint4*>(&BsL[kk*BSTR + co]) = lo;
            }
        }
    };

    auto compute = [&](int buf) {
        const uint32_t* AsH = smem + buf*CSZ;
        const uint32_t* AsL = AsH + A_WORDS;
        const uint32_t* BsH = AsH + NCOPY*A_WORDS;
        const uint32_t* BsL = BsH + B_WORDS;
        #pragma unroll
        for (int ks = 0; ks < BK; ks += 8) {
            uint32_t ah[MF][4], al[MF][4];
            #pragma unroll
            for (int i = 0; i < MF; i++) {
                int r = wm*WM + i*16 + lr;
                ah[i][0] = AsH[(r    )*ASTR + ks + lc];
                ah[i][1] = AsH[(r + 8)*ASTR + ks + lc];
                ah[i][2] = AsH[(r    )*ASTR + ks + lc + 4];
                ah[i][3] = AsH[(r + 8)*ASTR + ks + lc + 4];
                if (SPLIT == 3) {
                    al[i][0] = AsL[(r    )*ASTR + ks + lc];
                    al[i][1] = AsL[(r + 8)*ASTR + ks + lc];
                    al[i][2] = AsL[(r    )*ASTR + ks + lc + 4];
                    al[i][3] = AsL[(r + 8)*ASTR + ks + lc + 4];
                }
            }
            #pragma unroll
            for (int j = 0; j < NF; j++) {
                int c = wn*WN + j*8 + lr;
                uint32_t bh[2], bl[2];
                bh[0] = BsH[(ks + lc    )*BSTR + c];
                bh[1] = BsH[(ks + lc + 4)*BSTR + c];
                if (SPLIT == 3) {
                    bl[0] = BsL[(ks + lc    )*BSTR + c];
                    bl[1] = BsL[(ks + lc + 4)*BSTR + c];
                }
                #pragma unroll
                for (int i = 0; i < MF; i++) {
                    if (SPLIT == 3) {
                        mma_tf32(acc[i][j], al[i], bh);
                        mma_tf32(acc[i][j], ah[i], bl);
                    }
                    mma_tf32(acc[i][j], ah[i], bh);
                }
            }
        }
    };

    if (DB == 1) {
        load_regs(0);
        store_regs(0);
        __syncthreads();
        for (int s = 0; s < S; s++) {
            if (s + 1 < S) load_regs(s + 1);
            compute(s & 1);
            if (s + 1 < S) store_regs((s + 1) & 1);
            __syncthreads();
        }
    } else {
        load_regs(0);
        for (int s = 0; s < S; s++) {
            if (s > 0) __syncthreads();
            store_regs(0);
            __syncthreads();
            if (s + 1 < S) load_regs(s + 1);
            compute(0);
        }
    }

    // ---- epilogue ----
    #pragma unroll
    for (int i = 0; i < MF; i++) {
        int r0 = m0 + wm*WM + i*16 + lr;
        #pragma unroll
        for (int half = 0; half < 2; half++) {
            int mg = r0 + half*8;
            int obase;
            if (TRANS) {
                int mx = mg % MW; int t = mg / MW; int my = t % MH; int n = t / MH;
                obase = ((n*(2*INH) + 2*my + py)*(2*INW) + 2*mx + px)*COUT;
            } else {
                obase = mg*COUT;
            }
            #pragma unroll
            for (int j = 0; j < NF; j++) {
                int c = wn*WN + j*8 + 2*lc;
                float v0 = acc[i][j][half*2 + 0];
                float v1 = acc[i][j][half*2 + 1];
                if (HAS_BIAS) {
                    float2 bv = *reinterpret_cast<const float2*>(&bias[c]);
                    v0 += bv.x; v1 += bv.y;
                }
                if (ADD) {
                    float2 av = *reinterpret_cast<const float2*>(&addsrc[obase + c]);
                    v0 += av.x; v1 += av.y;
                }
                if (RELU_OUT) { v0 = fmaxf(v0, 0.f); v1 = fmaxf(v1, 0.f); }
                float2 ov; ov.x = v0; ov.y = v1;
                *reinterpret_cast<float2*>(&out[obase + c]) = ov;
            }
        }
    }
}

// ======================= codebook prep =======================
__global__ void emb_prep(const float* __restrict__ emb,
                         float* __restrict__ embT, float* __restrict__ ehalf)
{
    int c = blockIdx.x;
    int k = threadIdx.x;
    float v = emb[c*128 + k];
    embT[k*512 + c] = v;
    float s = v*v;
    #pragma unroll
    for (int o = 16; o; o >>= 1) s += __shfl_xor_sync(0xffffffffu, s, o);
    __shared__ float red[4];
    if ((k & 31) == 0) red[k >> 5] = s;
    __syncthreads();
    if (k == 0) ehalf[c] = 0.5f*(red[0]+red[1]+red[2]+red[3]);
}

// ======================= VQ via 3xTF32 tensor GEMM + fragment argmax =======================
// scores S[m,c] = f.e - ehalf (3xTF32: error ~2^-22, argmin-safe). Block = 128 rows,
// 512 codes in 4 n-chunks. Warps tile (wm, wn): wn halves see DIFFERENT column sets,
// so the argmax is reduced per-warp (quad shuffle), then ACROSS wn via shared memory.
__global__ void __launch_bounds__(256)
vq_mma(const float* __restrict__ f, const float* __restrict__ emb,
       const float* __restrict__ embT, const float* __restrict__ ehalf,
       float* __restrict__ q)
{
    constexpr int ASTR = 36, BSTR = 136;
    constexpr int A_WORDS = 128*ASTR, B_WORDS = 32*BSTR;
    extern __shared__ __align__(16) uint32_t vsm[];
    uint32_t* AsH = vsm;
    uint32_t* AsL = AsH + A_WORDS;
    uint32_t* BsH = AsL + A_WORDS;
    uint32_t* BsL = BsH + B_WORDS;
    __shared__ float bestV[128][2];
    __shared__ int   bestI[128][2];
    __shared__ int   rowIdx[128];

    const int tid  = threadIdx.x;
    const int wid  = tid >> 5;
    const int lane = tid & 31;
    const int lr   = lane >> 2;
    const int lc   = lane & 3;
    const int m0   = blockIdx.x * 128;
    const int wm   = wid >> 1;    // 0..3, WM=32
    const int wn   = wid & 1;     // 0..1, WN=64

    float best[4];
    int   bidx[4];
    #pragma unroll
    for (int t = 0; t < 4; t++) { best[t] = -3.4e38f; bidx[t] = 0; }

    for (int nc = 0; nc < 4; nc++) {
        float acc[2][8][4];
        #pragma unroll
        for (int i = 0; i < 2; i++)
            #pragma unroll
            for (int j = 0; j < 8; j++)
                #pragma unroll
                for (int r = 0; r < 4; r++) acc[i][j][r] = 0.f;

        for (int s = 0; s < 4; s++) {
            const int k0 = s*32;
            #pragma unroll
            for (int it = 0; it < 4; it++) {
                int l = tid + it*256;
                int m = l >> 3, kq = l & 7;
                float4 v = *reinterpret_cast<const float4*>(&f[(m0 + m)*128 + k0 + kq*4]);
                uint4 h;
                h.x = f2tf32(v.x); h.y = f2tf32(v.y); h.z = f2tf32(v.z); h.w = f2tf32(v.w);
                *reinterpret_cast<uint4*>(&AsH[m*ASTR + kq*4]) = h;
                uint4 lo;
                lo.x = f2tf32(v.x - __uint_as_float(h.x));
                lo.y = f2tf32(v.y - __uint_as_float(h.y));
                lo.z = f2tf32(v.z - __uint_as_float(h.z));
                lo.w = f2tf32(v.w - __uint_as_float(h.w));
                *reinterpret_cast<uint4*>(&AsL[m*ASTR + kq*4]) = lo;
            }
            #pragma unroll
            for (int it = 0; it < 4; it++) {
                int l = tid + it*256;
                int co = (l & 31)*4;
                int kk = l >> 5;
                float4 w = *reinterpret_cast<const float4*>(&embT[(k0 + kk)*512 + nc*128 + co]);
                uint4 h;
                h.x = f2tf32(w.x); h.y = f2tf32(w.y); h.z = f2tf32(w.z); h.w = f2tf32(w.w);
                *reinterpret_cast<uint4*>(&BsH[kk*BSTR + co]) = h;
                uint4 lo;
                lo.x = f2tf32(w.x - __uint_as_float(h.x));
                lo.y = f2tf32(w.y - __uint_as_float(h.y));
                lo.z = f2tf32(w.z - __uint_as_float(h.z));
                lo.w = f2tf32(w.w - __uint_as_float(h.w));
                *reinterpret_cast<uint4*>(&BsL[kk*BSTR + co]) = lo;
            }
            __syncthreads();
            #pragma unroll
            for (int ks = 0; ks < 32; ks += 8) {
                uint32_t ah[2][4], al[2][4];
                #pragma unroll
                for (int i = 0; i < 2; i++) {
                    int r = wm*32 + i*16 + lr;
                    ah[i][0] = AsH[(r    )*ASTR + ks + lc];
                    ah[i][1] = AsH[(r + 8)*ASTR + ks + lc];
                    ah[i][2] = AsH[(r    )*ASTR + ks + lc + 4];
                    ah[i][3] = AsH[(r + 8)*ASTR + ks + lc + 4];
                    al[i][0] = AsL[(r    )*ASTR + ks + lc];
                    al[i][1] = AsL[(r + 8)*ASTR + ks + lc];
                    al[i][2] = AsL[(r    )*ASTR + ks + lc + 4];
                    al[i][3] = AsL[(r + 8)*ASTR + ks + lc + 4];
                }
                #pragma unroll
                for (int j = 0; j < 8; j++) {
                    int c = wn*64 + j*8 + lr;
                    uint32_t bh[2], bl[2];
                    bh[0] = BsH[(ks + lc    )*BSTR + c];
                    bh[1] = BsH[(ks + lc + 4)*BSTR + c];
                    bl[0] = BsL[(ks + lc    )*BSTR + c];
                    bl[1] = BsL[(ks + lc + 4)*BSTR + c];
                    #pragma unroll
                    for (int i = 0; i < 2; i++) {
                        mma_tf32(acc[i][j], al[i], bh);
                        mma_tf32(acc[i][j], ah[i], bl);
                        mma_tf32(acc[i][j], ah[i], bh);
                    }
                }
            }
            __syncthreads();
        }
        // running argmax update for this n-chunk (this warp's column subset)
        #pragma unroll
        for (int i = 0; i < 2; i++) {
            #pragma unroll
            for (int half = 0; half < 2; half++) {
                int slot = i*2 + half;
                #pragma unroll
                for (int j = 0; j < 8; j++) {
                    int col = nc*128 + wn*64 + j*8 + 2*lc;
                    float s0 = acc[i][j][half*2 + 0] - __ldg(&ehalf[col]);
                    float s1 = acc[i][j][half*2 + 1] - __ldg(&ehalf[col + 1]);
                    if (s0 > best[slot] || (s0 == best[slot] && col < bidx[slot]))
                        { best[slot] = s0; bidx[slot] = col; }
                    if (s1 > best[slot] || (s1 == best[slot] && col + 1 < bidx[slot]))
                        { best[slot] = s1; bidx[slot] = col + 1; }
                }
            }
        }
    }
    // intra-warp reduce within quad (lanes lr*4+lc share the same row)
    #pragma unroll
    for (int slot = 0; slot < 4; slot++) {
        #pragma unroll
        for (int off = 1; off < 4; off <<= 1) {
            float ov = __shfl_xor_sync(0xffffffffu, best[slot], off);
            int   oi = __shfl_xor_sync(0xffffffffu, bidx[slot], off);
            if (ov > best[slot] || (ov == best[slot] && oi < bidx[slot]))
                { best[slot] = ov; bidx[slot] = oi; }
        }
        if (lc == 0) {
            int i = slot >> 1, half = slot & 1;
            int row = wm*32 + i*16 + half*8 + lr;
            bestV[row][wn] = best[slot];
            bestI[row][wn] = bidx[slot];
        }
    }
    __syncthreads();
    // cross-wn combine: each row's two half-codebook candidates -> final argmax
    for (int r = tid; r < 128; r += 256) {
        float v0 = bestV[r][0], v1 = bestV[r][1];
        int   i0 = bestI[r][0], i1 = bestI[r][1];
        rowIdx[r] = (v1 > v0 || (v1 == v0 && i1 < i0)) ? i1 : i0;
    }
    __syncthreads();
    // gather q rows
    for (int l = tid; l < 128*128; l += 256) {
        int r = l >> 7, j = l & 127;
        q[(m0 + r)*128 + j] = emb[rowIdx[r]*128 + j];
    }
}

// ======================= dt2: 4x4 s2 tconv 64->3, direct =======================
__global__ void __launch_bounds__(256)
dt2_kernel(const float* __restrict__ in,
           const float* __restrict__ wgt,
           const float* __restrict__ bias,
           float* __restrict__ out)
{
    __shared__ float ws[4*4*64*3];
    for (int l = threadIdx.x; l < 3072; l += 256) ws[l] = wgt[l];
    __syncthreads();

    const int py = blockIdx.z >> 1, px = blockIdx.z & 1;
    const int m = blockIdx.x * 256 + threadIdx.x;
    const int xq = m & 127; int t = m >> 7; const int yq = t & 127; const int n = t >> 7;

    float a0 = __ldg(&bias[0]), a1 = __ldg(&bias[1]), a2 = __ldg(&bias[2]);
    #pragma unroll
    for (int aa = 0; aa < 2; aa++) {
        #pragma unroll
        for (int bb = 0; bb < 2; bb++) {
            int iy = yq + py + aa - 1;
            int ix = xq + px + bb - 1;
            if (iy < 0 || iy >= 128 || ix < 0 || ix >= 128) continue;
            const float* ip = in + ((n*128 + iy)*128 + ix)*64;
            const float* wp = ws + ((2*aa + py)*4 + (2*bb + px))*64*3;
            #pragma unroll
            for (int ci = 0; ci < 64; ci += 4) {
                float4 v = *reinterpret_cast<const float4*>(ip + ci);
                const float* w0 = wp + ci*3;
                a0 += v.x*w0[0];  a1 += v.x*w0[1];  a2 += v.x*w0[2];
                a0 += v.y*w0[3];  a1 += v.y*w0[4];  a2 += v.y*w0[5];
                a0 += v.z*w0[6];  a1 += v.z*w0[7];  a2 += v.z*w0[8];
                a0 += v.w*w0[9];  a1 += v.w*w0[10]; a2 += v.w*w0[11];
            }
        }
    }
    const int oy = 2*yq + py, ox = 2*xq + px;
    float* op = out + ((n*256 + oy)*256 + ox)*3;
    op[0] = a0; op[1] = a1; op[2] = a2;
}

// ======================= host launcher =======================
extern "C" void kernel_launch(void* const* d_in, const int* in_sizes, int n_in,
                              void* d_out, int out_size)
{
    (void)in_sizes; (void)n_in;
    const float* x       = (const float*)d_in[0];
    const float* emb     = (const float*)d_in[1];
    const float* enc_w1  = (const float*)d_in[2];
    const float* enc_b1  = (const float*)d_in[3];
    const float* enc_w2  = (const float*)d_in[4];
    const float* enc_b2  = (const float*)d_in[5];
    const float* enc_w3  = (const float*)d_in[6];
    const float* enc_b3  = (const float*)d_in[7];
    const float* erb1_w1 = (const float*)d_in[8];
    const float* erb1_w2 = (const float*)d_in[9];
    const float* erb2_w1 = (const float*)d_in[10];
    const float* erb2_w2 = (const float*)d_in[11];
    const float* dec_w   = (const float*)d_in[12];
    const float* dec_b   = (const float*)d_in[13];
    const float* drb1_w1 = (const float*)d_in[14];
    const float* drb1_w2 = (const float*)d_in[15];
    const float* drb2_w1 = (const float*)d_in[16];
    const float* drb2_w2 = (const float*)d_in[17];
    const float* dt1_w   = (const float*)d_in[18];
    const float* dt1_b   = (const float*)d_in[19];
    const float* dt2_w   = (const float*)d_in[20];
    const float* dt2_b   = (const float*)d_in[21];

    float* out = (float*)d_out;
    const int YS = 16*256*256*3;
    const int FS = 16*64*64*128;

    float *buf0,*buf1,*buf2,*tmpb,*embT,*ehalf,*fb,*qb;
    cudaGetSymbolAddress((void**)&buf0,  g_buf0);
    cudaGetSymbolAddress((void**)&buf1,  g_buf1);
    cudaGetSymbolAddress((void**)&buf2,  g_buf2);
    cudaGetSymbolAddress((void**)&tmpb,  g_tmpb);
    cudaGetSymbolAddress((void**)&embT,  g_embT);
    cudaGetSymbolAddress((void**)&ehalf, g_ehalf);
    cudaGetSymbolAddress((void**)&fb,    g_fbuf);
    cudaGetSymbolAddress((void**)&qb,    g_qbuf);

    const bool full = (out_size >= YS + 2*FS);
    float* fptr = full ? (out + YS)      : fb;
    float* qptr = full ? (out + YS + FS) : qb;

    dim3 b(256);

    const int SM3_128_S = (2*128*36 + 2*32*136)*4;      // 71680, single-buffer
    const int SM3_32_D  = 2*(2*128*36 + 2*32*40)*4;     // 94208, double-buffer
    const int SM1_128_D = 2*(128*36 + 32*136)*4;        // 71680
    const int SM1_64_D  = 2*(128*36 + 32*72)*4;         // 55296
    const int SM1_32_D  = 2*(128*36 + 32*40)*4;         // 47104
    const int SM_VQ     = (2*128*36 + 2*32*136)*4;      // 71680

    // ---- encoder (3xTF32) ----
    auto kEnc2 = mma_conv3<64,128,4,4,2,1, 128,128, false,true,false,true,false,3,0>;
    auto kEnc3 = mma_conv3<128,128,3,3,1,1, 64,64, false,true,false,false,false,3,0>;
    auto kEw1  = mma_conv3<128,32, 3,3,1,1, 64,64, true,false,false,true,false,3,1>;
    auto kEw2  = mma_conv3<32,128, 1,1,1,0, 64,64, false,false,true,false,false,3,0>;
    auto kEw2R = mma_conv3<32,128, 1,1,1,0, 64,64, false,false,true,true,false,3,0>;
    // ---- decoder (single-pass tf32, double-buffered) ----
    auto kDec  = mma_conv3<128,128,3,3,1,1, 64,64, false,true,false,false,false,1,1>;
    auto kDw1  = mma_conv3<128,32, 3,3,1,1, 64,64, true,false,false,true,false,1,1>;
    auto kDw2  = mma_conv3<32,128, 1,1,1,0, 64,64, false,false,true,false,false,1,1>;
    auto kDw2R = mma_conv3<32,128, 1,1,1,0, 64,64, false,false,true,true,false,1,1>;
    auto kDt1  = mma_conv3<128,64, 4,4,2,0, 64,64, false,true,false,true,true,1,1>;

    cudaFuncSetAttribute(kEnc2, cudaFuncAttributeMaxDynamicSharedMemorySize, SM3_128_S);
    cudaFuncSetAttribute(kEnc3, cudaFuncAttributeMaxDynamicSharedMemorySize, SM3_128_S);
    cudaFuncSetAttribute(kEw1,  cudaFuncAttributeMaxDynamicSharedMemorySize, SM3_32_D);
    cudaFuncSetAttribute(kEw2,  cudaFuncAttributeMaxDynamicSharedMemorySize, SM3_128_S);
    cudaFuncSetAttribute(kEw2R, cudaFuncAttributeMaxDynamicSharedMemorySize, SM3_128_S);
    cudaFuncSetAttribute(kDec,  cudaFuncAttributeMaxDynamicSharedMemorySize, SM1_128_D);
    cudaFuncSetAttribute(kDw1,  cudaFuncAttributeMaxDynamicSharedMemorySize, SM1_32_D);
    cudaFuncSetAttribute(kDw2,  cudaFuncAttributeMaxDynamicSharedMemorySize, SM1_128_D);
    cudaFuncSetAttribute(kDw2R, cudaFuncAttributeMaxDynamicSharedMemorySize, SM1_128_D);
    cudaFuncSetAttribute(kDt1,  cudaFuncAttributeMaxDynamicSharedMemorySize, SM1_64_D);
    cudaFuncSetAttribute(vq_mma, cudaFuncAttributeMaxDynamicSharedMemorySize, SM_VQ);

    // ---- encoder ----
    conv_gemm<64,64,16,4,4,  3,64,4,4,2,1, 256,256,16, false,true,false,true,false>
        <<<dim3(4096,1,1),b>>>(x, enc_w1, enc_b1, nullptr, buf0);
    kEnc2<<<dim3(512,1,1), b, SM3_128_S>>>(buf0, enc_w2, enc_b2, nullptr, buf1);
    kEnc3<<<dim3(512,1,1), b, SM3_128_S>>>(buf1, enc_w3, enc_b3, nullptr, buf2);
    kEw1 <<<dim3(512,1,1), b, SM3_32_D >>>(buf2, erb1_w1, nullptr, nullptr, tmpb);
    kEw2 <<<dim3(512,1,1), b, SM3_128_S>>>(tmpb, erb1_w2, nullptr, buf2, buf2);
    kEw1 <<<dim3(512,1,1), b, SM3_32_D >>>(buf2, erb2_w1, nullptr, nullptr, tmpb);
    kEw2R<<<dim3(512,1,1), b, SM3_128_S>>>(tmpb, erb2_w2, nullptr, buf2, fptr);

    // ---- VQ (3xTF32 scores, fp32 norms, full-codebook argmax) ----
    emb_prep<<<512,128>>>(emb, embT, ehalf);
    vq_mma<<<512, b, SM_VQ>>>(fptr, emb, embT, ehalf, qptr);

    // ---- decoder ----
    kDec <<<dim3(512,1,1), b, SM1_128_D>>>(qptr, dec_w, dec_b, nullptr, buf1);
    kDw1 <<<dim3(512,1,1), b, SM1_32_D >>>(buf1, drb1_w1, nullptr, nullptr, tmpb);
    kDw2 <<<dim3(512,1,1), b, SM1_128_D>>>(tmpb, drb1_w2, nullptr, buf1, buf1);
    kDw1 <<<dim3(512,1,1), b, SM1_32_D >>>(buf1, drb2_w1, nullptr, nullptr, tmpb);
    kDw2R<<<dim3(512,1,1), b, SM1_128_D>>>(tmpb, drb2_w2, nullptr, buf1, buf2);
    kDt1 <<<dim3(512,1,4), b, SM1_64_D >>>(buf2, dt1_w, dt1_b, nullptr, buf0);

    dt2_kernel<<<dim3(1024,1,4),b>>>(buf0, dt2_w, dt2_b, out);
}